// round 5
// baseline (speedup 1.0000x reference)
#include <cuda_runtime.h>
#include <cuda_bf16.h>
#include <math.h>

// Problem constants
#define Hd     1024
#define Bd     64
#define Ld     256
#define KDIM   2048          // 2*H  (hl | hr)
#define NDIM   5120          // 5*H  (i | o | ck | fl | fr)
#define NLVL   8             // 256 -> 1
#define FOREST 255           // nodes per batch in forest_output

// ---- static device scratch (no allocations allowed) ----
__device__ float g_Wcat[(size_t)KDIM * NDIM];                 // packed weights (2048 x 5120)
__device__ float g_bcat[NDIM];                                // packed bias
__device__ float g_h0[(size_t)Bd * Ld * Hd];                  // level-0 input (embeddings)
__device__ float g_pre[(size_t)(Bd * Ld / 2) * NDIM];         // GEMM output, max M = 8192
__device__ float g_cbuf[2][(size_t)Bd * (Ld / 2) * Hd];       // c ping-pong

__device__ __forceinline__ float sigmoidf_(float x) {
    return 1.0f / (1.0f + expf(-x));
}

// ---------------------------------------------------------------------------
// 1) pack weights: Wcat[k][n]  (k<1024: W rows, else U rows; n: [iock|fl|fr])
// ---------------------------------------------------------------------------
__global__ void pack_weights_kernel(const float* __restrict__ W_iock,
                                    const float* __restrict__ U_iock,
                                    const float* __restrict__ W_fl,
                                    const float* __restrict__ U_fl,
                                    const float* __restrict__ W_fr,
                                    const float* __restrict__ U_fr,
                                    const float* __restrict__ b_iock,
                                    const float* __restrict__ b_fl,
                                    const float* __restrict__ b_fr) {
    size_t idx = (size_t)blockIdx.x * blockDim.x + threadIdx.x;
    if (idx >= (size_t)KDIM * NDIM) return;
    int n = (int)(idx % NDIM);
    int k = (int)(idx / NDIM);
    bool isW = (k < Hd);
    int kr = isW ? k : (k - Hd);
    float v;
    if (n < 3 * Hd) {
        v = isW ? W_iock[(size_t)kr * (3 * Hd) + n] : U_iock[(size_t)kr * (3 * Hd) + n];
    } else if (n < 4 * Hd) {
        int nn = n - 3 * Hd;
        v = isW ? W_fl[(size_t)kr * Hd + nn] : U_fl[(size_t)kr * Hd + nn];
    } else {
        int nn = n - 4 * Hd;
        v = isW ? W_fr[(size_t)kr * Hd + nn] : U_fr[(size_t)kr * Hd + nn];
    }
    g_Wcat[idx] = v;
    if (idx < NDIM) {
        int nb = (int)idx;
        g_bcat[nb] = (nb < 3 * Hd) ? b_iock[nb]
                   : (nb < 4 * Hd) ? b_fl[nb - 3 * Hd]
                                   : b_fr[nb - 4 * Hd];
    }
}

// ---------------------------------------------------------------------------
// 2) embedding gather: g_h0[b, l, :] = emb[tokens[b,l], :]   (float4 vectorized)
// ---------------------------------------------------------------------------
__global__ void embed_kernel(const int* __restrict__ tokens,
                             const float* __restrict__ emb) {
    int idx = blockIdx.x * blockDim.x + threadIdx.x;     // over B*L*(H/4)
    if (idx >= Bd * Ld * (Hd / 4)) return;
    int t = idx >> 8;           // / (H/4)
    int q = idx & 255;
    int tok = tokens[t];
    const float4* src = (const float4*)(emb + (size_t)tok * Hd);
    ((float4*)g_h0)[idx] = src[q];
}

// ---------------------------------------------------------------------------
// 3) per-level GEMM: pre(M,5120) = A(M,2048) @ g_Wcat + g_bcat
//    A row m: batch b = m/P, pair j = m%P, contiguous 2048 floats at
//      level==0 : g_h0  + b*(L*H)   + j*2048
//      level>=1 : dout  + (off_{lvl-1} + b*255)*H + j*2048
//    128x128x8 tile, 256 threads, 8x8 microtile.
// ---------------------------------------------------------------------------
__global__ __launch_bounds__(256)
void sgemm_kernel(const float* __restrict__ dout, int level) {
    const int P = 128 >> level;
    const int M = Bd * P;
    const float* Abase;
    size_t batchStride;
    if (level == 0) {
        Abase = g_h0;
        batchStride = (size_t)Ld * Hd;
    } else {
        int off_prev = 256 - (256 >> (level - 1));
        Abase = dout + (size_t)off_prev * Hd;
        batchStride = (size_t)FOREST * Hd;
    }

    __shared__ float As[8][128];
    __shared__ float Bs[8][128];

    const int tid = threadIdx.x;
    const int blockM = blockIdx.y * 128;
    const int blockN = blockIdx.x * 128;

    // A staging: thread -> (row = tid/2, k quad = (tid&1)*4)
    const int a_row = tid >> 1;
    const int a_k = (tid & 1) * 4;
    const float* a_ptr = nullptr;
    {
        int gm = blockM + a_row;
        if (gm < M) {
            int b = gm / P;
            int j = gm - b * P;
            a_ptr = Abase + (size_t)b * batchStride + (size_t)j * KDIM + a_k;
        }
    }
    // B staging: thread -> (k = tid/32, col quad = (tid&31)*4)
    const int b_k = tid >> 5;
    const int b_col = (tid & 31) * 4;
    const float* b_ptr = g_Wcat + (size_t)b_k * NDIM + blockN + b_col;

    const int tr = (tid >> 4) * 8;   // micro-tile row offset
    const int tc = (tid & 15) * 8;   // micro-tile col offset

    float acc[8][8];
#pragma unroll
    for (int i = 0; i < 8; i++)
#pragma unroll
        for (int j = 0; j < 8; j++) acc[i][j] = 0.0f;

    for (int k0 = 0; k0 < KDIM; k0 += 8) {
        float4 av = a_ptr ? *(const float4*)(a_ptr + k0) : make_float4(0.f, 0.f, 0.f, 0.f);
        float4 bv = *(const float4*)(b_ptr + (size_t)k0 * NDIM);
        __syncthreads();
        As[a_k + 0][a_row] = av.x;
        As[a_k + 1][a_row] = av.y;
        As[a_k + 2][a_row] = av.z;
        As[a_k + 3][a_row] = av.w;
        *(float4*)&Bs[b_k][b_col] = bv;
        __syncthreads();
#pragma unroll
        for (int kk = 0; kk < 8; ++kk) {
            float4 a0 = *(const float4*)&As[kk][tr];
            float4 a1 = *(const float4*)&As[kk][tr + 4];
            float4 q0 = *(const float4*)&Bs[kk][tc];
            float4 q1 = *(const float4*)&Bs[kk][tc + 4];
            float ar[8] = {a0.x, a0.y, a0.z, a0.w, a1.x, a1.y, a1.z, a1.w};
            float br[8] = {q0.x, q0.y, q0.z, q0.w, q1.x, q1.y, q1.z, q1.w};
#pragma unroll
            for (int i = 0; i < 8; i++)
#pragma unroll
                for (int j = 0; j < 8; j++) acc[i][j] = fmaf(ar[i], br[j], acc[i][j]);
        }
    }

    // epilogue: += bias, store to g_pre
#pragma unroll
    for (int i = 0; i < 8; i++) {
        int gm = blockM + tr + i;
        if (gm >= M) continue;
        float* crow = g_pre + (size_t)gm * NDIM + blockN + tc;
#pragma unroll
        for (int j = 0; j < 8; j += 4) {
            float4 v;
            v.x = acc[i][j + 0] + g_bcat[blockN + tc + j + 0];
            v.y = acc[i][j + 1] + g_bcat[blockN + tc + j + 1];
            v.z = acc[i][j + 2] + g_bcat[blockN + tc + j + 2];
            v.w = acc[i][j + 3] + g_bcat[blockN + tc + j + 3];
            *(float4*)(crow + j) = v;
        }
    }
}

// ---------------------------------------------------------------------------
// 4) gates: c = sig(i)*tanh(ck) + sig(fl)*cl + sig(fr)*cr ; h = sig(o)*tanh(c)
//    writes h into d_out forest slice (and root h/c for the last level)
// ---------------------------------------------------------------------------
__global__ void gates_kernel(float* __restrict__ dout, int level) {
    const int P = 128 >> level;
    const int M = Bd * P;
    int idx = blockIdx.x * blockDim.x + threadIdx.x;
    if (idx >= M * Hd) return;
    int m = idx >> 10;
    int col = idx & (Hd - 1);

    const float* prow = g_pre + (size_t)m * NDIM;
    float p_i = prow[col];
    float p_o = prow[col + 1024];
    float p_k = prow[col + 2048];
    float p_fl = prow[col + 3072];
    float p_fr = prow[col + 4096];

    float cl = 0.f, cr = 0.f;
    if (level > 0) {
        const float* cp = g_cbuf[(level - 1) & 1];
        cl = cp[(size_t)m * KDIM + col];
        cr = cp[(size_t)m * KDIM + Hd + col];
    }

    float ig = sigmoidf_(p_i);
    float og = sigmoidf_(p_o);
    float ck = tanhf(p_k);
    float fl = sigmoidf_(p_fl);
    float fr = sigmoidf_(p_fr);
    float c = ig * ck + fl * cl + fr * cr;
    float h = og * tanhf(c);

    g_cbuf[level & 1][(size_t)m * Hd + col] = c;

    int b = m / P;
    int j = m - b * P;
    int off = 256 - (256 >> level);
    dout[((size_t)b * FOREST + off + j) * Hd + col] = h;

    if (level == NLVL - 1) {
        // root: m == b, P == 1. h_root (1,B,H) then c_root (1,B,H) after forest.
        float* hroot = dout + (size_t)Bd * FOREST * Hd;
        float* croot = hroot + (size_t)Bd * Hd;
        hroot[idx] = h;
        croot[idx] = c;
    }
}

// ---------------------------------------------------------------------------
// launcher (graph-capturable: kernel launches only, default stream)
// ---------------------------------------------------------------------------
extern "C" void kernel_launch(void* const* d_in, const int* in_sizes, int n_in,
                              void* d_out, int out_size) {
    const int*   tokens = (const int*)  d_in[0];
    const float* emb    = (const float*)d_in[1];
    const float* W_iock = (const float*)d_in[2];
    const float* b_iock = (const float*)d_in[3];
    const float* U_iock = (const float*)d_in[4];
    const float* W_fl   = (const float*)d_in[5];
    const float* b_fl   = (const float*)d_in[6];
    const float* U_fl   = (const float*)d_in[7];
    const float* W_fr   = (const float*)d_in[8];
    const float* b_fr   = (const float*)d_in[9];
    const float* U_fr   = (const float*)d_in[10];
    float* out = (float*)d_out;

    // pack weights + bias
    {
        size_t total = (size_t)KDIM * NDIM;
        int blocks = (int)((total + 255) / 256);
        pack_weights_kernel<<<blocks, 256>>>(W_iock, U_iock, W_fl, U_fl, W_fr, U_fr,
                                             b_iock, b_fl, b_fr);
    }
    // embedding gather
    {
        int total = Bd * Ld * (Hd / 4);
        embed_kernel<<<(total + 255) / 256, 256>>>(tokens, emb);
    }
    // level sweep
    for (int level = 0; level < NLVL; ++level) {
        int P = 128 >> level;
        int M = Bd * P;
        dim3 grid(NDIM / 128, (M + 127) / 128);
        sgemm_kernel<<<grid, 256>>>(out, level);
        int total = M * Hd;
        gates_kernel<<<(total + 255) / 256, 256>>>(out, level);
    }
}

// round 7
// speedup vs baseline: 2.3570x; 2.3570x over previous
#include <cuda_runtime.h>
#include <cuda_bf16.h>
#include <cstdint>
#include <math.h>

#define Hd     1024
#define Bd     64
#define NDIM   5120
#define FOREST 255
#define KTOT   2048
#define STAGE_BYTES 61440          // A: 2*10240, B: 2*20480
#define NSTAGE 3
#define SMEMT  (NSTAGE * STAGE_BYTES)   // 184320 bytes

// ---------------- static device scratch ----------------
__device__ __nv_bfloat16 g_Ah[(size_t)16384 * 2048];   // A hi, row-major [row][k]
__device__ __nv_bfloat16 g_Al[(size_t)16384 * 2048];   // A lo
__device__ __nv_bfloat16 g_Wh[(size_t)5120 * 2048];    // W^T hi, [n][k]
__device__ __nv_bfloat16 g_Wl[(size_t)5120 * 2048];    // W^T lo
__device__ float g_bcat[NDIM];
__device__ float g_pre[(size_t)8192 * NDIM];
__device__ float g_cbuf[2][(size_t)8192 * Hd];

// ---------------- helpers ----------------
__device__ __forceinline__ uint32_t smem_u32(const void* p) {
    uint32_t a;
    asm("{ .reg .u64 t; cvta.to.shared.u64 t, %1; cvt.u32.u64 %0, t; }" : "=r"(a) : "l"(p));
    return a;
}
__device__ __forceinline__ void cpasync16(uint32_t dst, const void* src) {
    asm volatile("cp.async.cg.shared.global [%0], [%1], 16;" :: "r"(dst), "l"(src));
}
__device__ __forceinline__ void ldsm4(uint32_t* r, uint32_t addr) {
    asm volatile("ldmatrix.sync.aligned.m8n8.x4.shared.b16 {%0,%1,%2,%3}, [%4];"
                 : "=r"(r[0]), "=r"(r[1]), "=r"(r[2]), "=r"(r[3]) : "r"(addr));
}
__device__ __forceinline__ void mma16816(float* c, const uint32_t* a, const uint32_t* b) {
    asm volatile("mma.sync.aligned.m16n8k16.row.col.f32.bf16.bf16.f32 "
                 "{%0,%1,%2,%3}, {%4,%5,%6,%7}, {%8,%9}, {%0,%1,%2,%3};"
                 : "+f"(c[0]), "+f"(c[1]), "+f"(c[2]), "+f"(c[3])
                 : "r"(a[0]), "r"(a[1]), "r"(a[2]), "r"(a[3]), "r"(b[0]), "r"(b[1]));
}
__device__ __forceinline__ uint32_t pk2(__nv_bfloat16 a, __nv_bfloat16 b) {
    __nv_bfloat162 t(a, b);
    return *reinterpret_cast<uint32_t*>(&t);
}
// 8 fp32 -> packed bf16 hi uint4 + lo uint4
__device__ __forceinline__ void cvt8(const float* f, uint4& hv, uint4& lv) {
    uint32_t hw[4], lw[4];
#pragma unroll
    for (int q = 0; q < 4; q++) {
        float a = f[2*q], b = f[2*q+1];
        __nv_bfloat16 ha = __float2bfloat16(a), hb = __float2bfloat16(b);
        hw[q] = pk2(ha, hb);
        lw[q] = pk2(__float2bfloat16(a - __bfloat162float(ha)),
                    __float2bfloat16(b - __bfloat162float(hb)));
    }
    hv = make_uint4(hw[0], hw[1], hw[2], hw[3]);
    lv = make_uint4(lw[0], lw[1], lw[2], lw[3]);
}
__device__ __forceinline__ float sigf(float x)   { return 1.0f / (1.0f + __expf(-x)); }
__device__ __forceinline__ float tanhf_(float x) { return 2.0f / (1.0f + __expf(-2.0f * x)) - 1.0f; }

// ---------------------------------------------------------------------------
// Weight pack with smem transpose: g_W{h,l}[n][k] = cat(W;U)[k][n] split to hi/lo.
// Block = 64k x 64n tile. grid = (32 k-tiles, 80 n-tiles).
// ---------------------------------------------------------------------------
__global__ __launch_bounds__(256)
void pack_w_kernel(const float* __restrict__ Wi, const float* __restrict__ Ui,
                   const float* __restrict__ Wfl, const float* __restrict__ Ufl,
                   const float* __restrict__ Wfr, const float* __restrict__ Ufr) {
    __shared__ float ts[64][65];
    int k0 = blockIdx.x * 64, n0 = blockIdx.y * 64;
    const float *Wm, *Um; int st, nc0;
    if (n0 < 3072)      { Wm = Wi;  Um = Ui;  st = 3072; nc0 = n0; }
    else if (n0 < 4096) { Wm = Wfl; Um = Ufl; st = 1024; nc0 = n0 - 3072; }
    else                { Wm = Wfr; Um = Ufr; st = 1024; nc0 = n0 - 4096; }
    const float* base = (k0 < 1024) ? Wm : Um;
    int kr0 = k0 & 1023;
    for (int e = threadIdx.x; e < 4096; e += 256) {
        int r = e >> 6, c = e & 63;
        ts[r][c] = base[(size_t)(kr0 + r) * st + nc0 + c];
    }
    __syncthreads();
    for (int u = threadIdx.x; u < 512; u += 256) {
        int nr = u >> 3, ko = u & 7;
        float f[8];
#pragma unroll
        for (int i = 0; i < 8; i++) f[i] = ts[ko * 8 + i][nr];
        uint4 hv, lv; cvt8(f, hv, lv);
        size_t off = (size_t)(n0 + nr) * KTOT + k0 + ko * 8;
        *(uint4*)(g_Wh + off) = hv;
        *(uint4*)(g_Wl + off) = lv;
    }
}

__global__ void pack_b_kernel(const float* __restrict__ bi,
                              const float* __restrict__ bfl,
                              const float* __restrict__ bfr) {
    int n = blockIdx.x * 256 + threadIdx.x;
    if (n >= NDIM) return;
    g_bcat[n] = (n < 3072) ? bi[n] : (n < 4096) ? bfl[n - 3072] : bfr[n - 4096];
}

// ---------------------------------------------------------------------------
// Embedding: write level-0 A rows (hi/lo bf16). Row r = b*128 + (l>>1),
// k-half = (l&1)*1024.
// ---------------------------------------------------------------------------
__global__ __launch_bounds__(256)
void embed_kernel(const int* __restrict__ tokens, const float* __restrict__ emb) {
    int idx = blockIdx.x * 256 + threadIdx.x;     // B*256*128 units of 8 elems
    if (idx >= Bd * 256 * 128) return;
    int u = idx & 127, t = idx >> 7;
    int b = t >> 8, l = t & 255;
    int tok = tokens[t];
    const float* s = emb + (size_t)tok * Hd + u * 8;
    float f[8];
    *(float4*)f       = *(const float4*)s;
    *(float4*)(f + 4) = *(const float4*)(s + 4);
    uint4 hv, lv; cvt8(f, hv, lv);
    int r = b * 128 + (l >> 1);
    size_t off = (size_t)r * KTOT + (l & 1) * 1024 + u * 8;
    *(uint4*)(g_Ah + off) = hv;
    *(uint4*)(g_Al + off) = lv;
}

// ---------------------------------------------------------------------------
// HMMA GEMM: pre(M,5120) = A(M,2048) @ W^T, bf16 hi/lo 3-pass, fp32 acc.
// CTA 128M x 256N, 8 warps (2x4) of 64x64, k32 chunks, 3-stage cp.async.
// smem per stage: Ah[128x40bf16] Al | Bh[256x40] Bl  (pitch 80B, conflict-free
// for ldmatrix: row-start bank-quads cycle {0,5,2,7,4,1,6,3}).
// ---------------------------------------------------------------------------
__global__ __launch_bounds__(256, 1)
void gemm_kernel(int level) {
    extern __shared__ char smraw[];
    const uint32_t smb = smem_u32(smraw);
    const int tid = threadIdx.x, lane = tid & 31, wid = tid >> 5;
    const int wm = wid >> 2, wn = wid & 3;
    const int M = Bd * (128 >> level);
    const int mt = blockIdx.x, bn = blockIdx.y;
    const size_t aRow0 = (size_t)(16384 - (16384 >> level)) + (size_t)mt * 128;
    const size_t bRow0 = (size_t)bn * 256;

    const int lc = tid & 3;          // 16B chunk within k32
    const int lr = tid >> 2;         // 0..63

    float acc[4][8][4];
#pragma unroll
    for (int a = 0; a < 4; a++)
#pragma unroll
        for (int b = 0; b < 8; b++)
#pragma unroll
            for (int c = 0; c < 4; c++) acc[a][b][c] = 0.0f;

    // ldmatrix per-thread base addresses (A: 16x16 tiles; B: n16 x k16 tiles)
    const uint32_t aB = smb + (wm * 64 + (lane & 15)) * 80 + (lane >> 4) * 16;
    const uint32_t bB = smb + 20480
                      + (wn * 64 + (lane & 7) + ((lane >> 4) << 3)) * 80
                      + ((lane >> 3) & 1) * 16;

    auto load_stage = [&](int s, int kb) {
        uint32_t st = smb + s * STAGE_BYTES;
#pragma unroll
        for (int i = 0; i < 2; i++) {                  // A: 128 rows
            int row = lr + i * 64;
            size_t go = (aRow0 + row) * KTOT + kb + lc * 8;
            uint32_t d = st + row * 80 + lc * 16;
            cpasync16(d,         g_Ah + go);
            cpasync16(d + 10240, g_Al + go);
        }
#pragma unroll
        for (int i = 0; i < 4; i++) {                  // B: 256 rows
            int row = lr + i * 64;
            size_t go = (bRow0 + row) * KTOT + kb + lc * 8;
            uint32_t d = st + 20480 + row * 80 + lc * 16;
            cpasync16(d,         g_Wh + go);
            cpasync16(d + 20480, g_Wl + go);
        }
        asm volatile("cp.async.commit_group;" ::: "memory");
    };

    load_stage(0, 0);
    load_stage(1, 32);

    for (int ks = 0; ks < 64; ks++) {
        asm volatile("cp.async.wait_group 1;" ::: "memory");
        __syncthreads();
        if (ks + 2 < 64) load_stage((ks + 2) % 3, (ks + 2) * 32);
        else asm volatile("cp.async.commit_group;" ::: "memory");

        uint32_t sOff = (uint32_t)(ks % 3) * STAGE_BYTES;
#pragma unroll
        for (int sub = 0; sub < 2; sub++) {
            uint32_t aS = aB + sOff + sub * 32;
            uint32_t bS = bB + sOff + sub * 32;
            uint32_t ah[4][4], al[4][4];
#pragma unroll
            for (int mb = 0; mb < 4; mb++) {
                ldsm4(ah[mb], aS + mb * 1280);
                ldsm4(al[mb], aS + mb * 1280 + 10240);
            }
#pragma unroll
            for (int nbp = 0; nbp < 4; nbp++) {
                uint32_t bh[4], bl[4];
                ldsm4(bh, bS + nbp * 1280);
                ldsm4(bl, bS + nbp * 1280 + 20480);
#pragma unroll
                for (int mb = 0; mb < 4; mb++) {
                    mma16816(acc[mb][2*nbp],   ah[mb], bh);
                    mma16816(acc[mb][2*nbp+1], ah[mb], bh + 2);
                    mma16816(acc[mb][2*nbp],   al[mb], bh);
                    mma16816(acc[mb][2*nbp+1], al[mb], bh + 2);
                    mma16816(acc[mb][2*nbp],   ah[mb], bl);
                    mma16816(acc[mb][2*nbp+1], ah[mb], bl + 2);
                }
            }
        }
    }

    // epilogue: direct STG (guarded for M=64 tail level)
    const int gm0 = mt * 128 + wm * 64;
    const int gn0 = bn * 256 + wn * 64;
#pragma unroll
    for (int mb = 0; mb < 4; mb++) {
        int r0 = gm0 + mb * 16 + (lane >> 2);
#pragma unroll
        for (int nb = 0; nb < 8; nb++) {
            int cc = gn0 + nb * 8 + (lane & 3) * 2;
            if (r0 < M) {
                float2 v = make_float2(acc[mb][nb][0], acc[mb][nb][1]);
                *(float2*)(g_pre + (size_t)r0 * NDIM + cc) = v;
            }
            if (r0 + 8 < M) {
                float2 v = make_float2(acc[mb][nb][2], acc[mb][nb][3]);
                *(float2*)(g_pre + (size_t)(r0 + 8) * NDIM + cc) = v;
            }
        }
    }
}

// ---------------------------------------------------------------------------
// Gates: bias + LSTM gate math; writes h (fp32) to d_out, c to ping-pong,
// and h as next-level A rows (bf16 hi/lo).
// ---------------------------------------------------------------------------
__global__ __launch_bounds__(256)
void gates_kernel(float* __restrict__ dout, int level) {
    const int P = 128 >> level;
    const int M = Bd * P;
    int idx = blockIdx.x * 256 + threadIdx.x;
    if (idx >= M * 128) return;
    int m = idx >> 7, u = idx & 127;
    int col0 = u << 3;

    const float* prow = g_pre + (size_t)m * NDIM + col0;
    float pi[8], po[8], pk[8], pl[8], pr[8];
    *(float4*)pi = *(const float4*)(prow);          *(float4*)(pi+4) = *(const float4*)(prow + 4);
    *(float4*)po = *(const float4*)(prow + 1024);   *(float4*)(po+4) = *(const float4*)(prow + 1028);
    *(float4*)pk = *(const float4*)(prow + 2048);   *(float4*)(pk+4) = *(const float4*)(prow + 2052);
    *(float4*)pl = *(const float4*)(prow + 3072);   *(float4*)(pl+4) = *(const float4*)(prow + 3076);
    *(float4*)pr = *(const float4*)(prow + 4096);   *(float4*)(pr+4) = *(const float4*)(prow + 4100);

    const float* bb = g_bcat + col0;
    float bi[8], bo[8], bk[8], bl[8], br[8];
    *(float4*)bi = *(const float4*)(bb);          *(float4*)(bi+4) = *(const float4*)(bb + 4);
    *(float4*)bo = *(const float4*)(bb + 1024);   *(float4*)(bo+4) = *(const float4*)(bb + 1028);
    *(float4*)bk = *(const float4*)(bb + 2048);   *(float4*)(bk+4) = *(const float4*)(bb + 2052);
    *(float4*)bl = *(const float4*)(bb + 3072);   *(float4*)(bl+4) = *(const float4*)(bb + 3076);
    *(float4*)br = *(const float4*)(bb + 4096);   *(float4*)(br+4) = *(const float4*)(bb + 4100);

    float cl[8] = {0,0,0,0,0,0,0,0}, cr[8] = {0,0,0,0,0,0,0,0};
    if (level > 0) {
        const float* cp = g_cbuf[(level + 1) & 1] + (size_t)m * 2048 + col0;
        *(float4*)cl = *(const float4*)(cp);         *(float4*)(cl+4) = *(const float4*)(cp + 4);
        *(float4*)cr = *(const float4*)(cp + 1024);  *(float4*)(cr+4) = *(const float4*)(cp + 1028);
    }

    float cv[8], hv[8];
#pragma unroll
    for (int i = 0; i < 8; i++) {
        float c = sigf(pi[i] + bi[i]) * tanhf_(pk[i] + bk[i])
                + sigf(pl[i] + bl[i]) * cl[i]
                + sigf(pr[i] + br[i]) * cr[i];
        cv[i] = c;
        hv[i] = sigf(po[i] + bo[i]) * tanhf_(c);
    }

    float* cw = g_cbuf[level & 1] + (size_t)m * Hd + col0;
    *(float4*)cw = *(const float4*)cv;  *(float4*)(cw + 4) = *(const float4*)(cv + 4);

    int b = m >> (7 - level);
    int j = m & (P - 1);
    int off = 256 - (256 >> level);
    float* hw = dout + ((size_t)b * FOREST + off + j) * Hd + col0;
    *(float4*)hw = *(const float4*)hv;  *(float4*)(hw + 4) = *(const float4*)(hv + 4);

    if (level < 7) {
        int r = b * (P >> 1) + (j >> 1);
        size_t rowbase = 16384 - (16384 >> (level + 1));
        size_t aoff = (rowbase + r) * (size_t)KTOT + (j & 1) * 1024 + col0;
        uint4 hvv, lvv; cvt8(hv, hvv, lvv);
        *(uint4*)(g_Ah + aoff) = hvv;
        *(uint4*)(g_Al + aoff) = lvv;
    } else {
        float* hroot = dout + (size_t)Bd * FOREST * Hd + (size_t)m * Hd + col0;
        float* croot = hroot + (size_t)Bd * Hd;
        *(float4*)hroot = *(const float4*)hv;  *(float4*)(hroot + 4) = *(const float4*)(hv + 4);
        *(float4*)croot = *(const float4*)cv;  *(float4*)(croot + 4) = *(const float4*)(cv + 4);
    }
}

// ---------------------------------------------------------------------------
// launcher (graph-capturable: kernel launches only, default stream)
// ---------------------------------------------------------------------------
extern "C" void kernel_launch(void* const* d_in, const int* in_sizes, int n_in,
                              void* d_out, int out_size) {
    const int*   tokens = (const int*)  d_in[0];
    const float* emb    = (const float*)d_in[1];
    const float* W_iock = (const float*)d_in[2];
    const float* b_iock = (const float*)d_in[3];
    const float* U_iock = (const float*)d_in[4];
    const float* W_fl   = (const float*)d_in[5];
    const float* b_fl   = (const float*)d_in[6];
    const float* U_fl   = (const float*)d_in[7];
    const float* W_fr   = (const float*)d_in[8];
    const float* b_fr   = (const float*)d_in[9];
    const float* U_fr   = (const float*)d_in[10];
    float* out = (float*)d_out;

    static bool attr_set = false;
    if (!attr_set) {
        cudaFuncSetAttribute(gemm_kernel, cudaFuncAttributeMaxDynamicSharedMemorySize, SMEMT);
        attr_set = true;
    }

    pack_w_kernel<<<dim3(32, 80), 256>>>(W_iock, U_iock, W_fl, U_fl, W_fr, U_fr);
    pack_b_kernel<<<20, 256>>>(b_iock, b_fl, b_fr);
    {
        int total = Bd * 256 * 128;
        embed_kernel<<<(total + 255) / 256, 256>>>(tokens, emb);
    }
    for (int level = 0; level < 8; ++level) {
        int M = Bd * (128 >> level);
        dim3 grid((M + 127) / 128, 20);
        gemm_kernel<<<grid, 256, SMEMT>>>(level);
        int units = M * 128;
        gates_kernel<<<(units + 255) / 256, 256>>>(out, level);
    }
}

// round 8
// speedup vs baseline: 2.3982x; 1.0175x over previous
#include <cuda_runtime.h>
#include <cuda_bf16.h>
#include <cstdint>
#include <math.h>

#define Hd     1024
#define Bd     64
#define NDIM   5120
#define FOREST 255
#define KTOT   2048
#define STAGE_BYTES 61440          // A: 2*10240, B: 2*20480
#define NSTAGE 3
#define SMEMT  (NSTAGE * STAGE_BYTES)   // 184320 bytes

// ---------------- static device scratch ----------------
__device__ __nv_bfloat16 g_Ah[(size_t)16384 * 2048];   // A hi, row-major [row][k]
__device__ __nv_bfloat16 g_Al[(size_t)16384 * 2048];   // A lo
__device__ __nv_bfloat16 g_Wh[(size_t)5120 * 2048];    // W^T hi, [n][k]
__device__ __nv_bfloat16 g_Wl[(size_t)5120 * 2048];    // W^T lo
__device__ float g_bcat[NDIM];
__device__ float g_pre[(size_t)8192 * NDIM];
__device__ float g_cbuf[2][(size_t)8192 * Hd];

// ---------------- helpers ----------------
__device__ __forceinline__ uint32_t smem_u32(const void* p) {
    uint32_t a;
    asm("{ .reg .u64 t; cvta.to.shared.u64 t, %1; cvt.u32.u64 %0, t; }" : "=r"(a) : "l"(p));
    return a;
}
__device__ __forceinline__ void cpasync16(uint32_t dst, const void* src) {
    asm volatile("cp.async.cg.shared.global [%0], [%1], 16;" :: "r"(dst), "l"(src));
}
__device__ __forceinline__ void ldsm4(uint32_t* r, uint32_t addr) {
    asm volatile("ldmatrix.sync.aligned.m8n8.x4.shared.b16 {%0,%1,%2,%3}, [%4];"
                 : "=r"(r[0]), "=r"(r[1]), "=r"(r[2]), "=r"(r[3]) : "r"(addr));
}
__device__ __forceinline__ void mma16816(float* c, const uint32_t* a, const uint32_t* b) {
    asm volatile("mma.sync.aligned.m16n8k16.row.col.f32.bf16.bf16.f32 "
                 "{%0,%1,%2,%3}, {%4,%5,%6,%7}, {%8,%9}, {%0,%1,%2,%3};"
                 : "+f"(c[0]), "+f"(c[1]), "+f"(c[2]), "+f"(c[3])
                 : "r"(a[0]), "r"(a[1]), "r"(a[2]), "r"(a[3]), "r"(b[0]), "r"(b[1]));
}
__device__ __forceinline__ uint32_t pk2(__nv_bfloat16 a, __nv_bfloat16 b) {
    __nv_bfloat162 t(a, b);
    return *reinterpret_cast<uint32_t*>(&t);
}
// 8 fp32 -> packed bf16 hi uint4 + lo uint4
__device__ __forceinline__ void cvt8(const float* f, uint4& hv, uint4& lv) {
    uint32_t hw[4], lw[4];
#pragma unroll
    for (int q = 0; q < 4; q++) {
        float a = f[2*q], b = f[2*q+1];
        __nv_bfloat16 ha = __float2bfloat16(a), hb = __float2bfloat16(b);
        hw[q] = pk2(ha, hb);
        lw[q] = pk2(__float2bfloat16(a - __bfloat162float(ha)),
                    __float2bfloat16(b - __bfloat162float(hb)));
    }
    hv = make_uint4(hw[0], hw[1], hw[2], hw[3]);
    lv = make_uint4(lw[0], lw[1], lw[2], lw[3]);
}
__device__ __forceinline__ float sigf(float x)   { return 1.0f / (1.0f + __expf(-x)); }
__device__ __forceinline__ float tanhf_(float x) { return 2.0f / (1.0f + __expf(-2.0f * x)) - 1.0f; }

// ---------------------------------------------------------------------------
// Weight pack with smem transpose: g_W{h,l}[n][k] = cat(W;U)[k][n] split to hi/lo.
// ---------------------------------------------------------------------------
__global__ __launch_bounds__(256)
void pack_w_kernel(const float* __restrict__ Wi, const float* __restrict__ Ui,
                   const float* __restrict__ Wfl, const float* __restrict__ Ufl,
                   const float* __restrict__ Wfr, const float* __restrict__ Ufr) {
    __shared__ float ts[64][65];
    int k0 = blockIdx.x * 64, n0 = blockIdx.y * 64;
    const float *Wm, *Um; int st, nc0;
    if (n0 < 3072)      { Wm = Wi;  Um = Ui;  st = 3072; nc0 = n0; }
    else if (n0 < 4096) { Wm = Wfl; Um = Ufl; st = 1024; nc0 = n0 - 3072; }
    else                { Wm = Wfr; Um = Ufr; st = 1024; nc0 = n0 - 4096; }
    const float* base = (k0 < 1024) ? Wm : Um;
    int kr0 = k0 & 1023;
    for (int e = threadIdx.x; e < 4096; e += 256) {
        int r = e >> 6, c = e & 63;
        ts[r][c] = base[(size_t)(kr0 + r) * st + nc0 + c];
    }
    __syncthreads();
    for (int u = threadIdx.x; u < 512; u += 256) {
        int nr = u >> 3, ko = u & 7;
        float f[8];
#pragma unroll
        for (int i = 0; i < 8; i++) f[i] = ts[ko * 8 + i][nr];
        uint4 hv, lv; cvt8(f, hv, lv);
        size_t off = (size_t)(n0 + nr) * KTOT + k0 + ko * 8;
        *(uint4*)(g_Wh + off) = hv;
        *(uint4*)(g_Wl + off) = lv;
    }
}

__global__ void pack_b_kernel(const float* __restrict__ bi,
                              const float* __restrict__ bfl,
                              const float* __restrict__ bfr) {
    int n = blockIdx.x * 256 + threadIdx.x;
    if (n >= NDIM) return;
    g_bcat[n] = (n < 3072) ? bi[n] : (n < 4096) ? bfl[n - 3072] : bfr[n - 4096];
}

// ---------------------------------------------------------------------------
// Embedding: write level-0 A rows (hi/lo bf16). Row r = b*128 + (l>>1),
// k-half = (l&1)*1024.
// ---------------------------------------------------------------------------
__global__ __launch_bounds__(256)
void embed_kernel(const int* __restrict__ tokens, const float* __restrict__ emb) {
    int idx = blockIdx.x * 256 + threadIdx.x;     // B*256*128 units of 8 elems
    if (idx >= Bd * 256 * 128) return;
    int u = idx & 127, t = idx >> 7;
    int b = t >> 8, l = t & 255;
    int tok = tokens[t];
    const float* s = emb + (size_t)tok * Hd + u * 8;
    float f[8];
    *(float4*)f       = *(const float4*)s;
    *(float4*)(f + 4) = *(const float4*)(s + 4);
    uint4 hv, lv; cvt8(f, hv, lv);
    int r = b * 128 + (l >> 1);
    size_t off = (size_t)r * KTOT + (l & 1) * 1024 + u * 8;
    *(uint4*)(g_Ah + off) = hv;
    *(uint4*)(g_Al + off) = lv;
}

// ---------------------------------------------------------------------------
// HMMA GEMM: pre(M,5120) = A(M,2048) @ W^T, bf16 hi/lo 3-pass, fp32 acc.
// CTA 128M x 256N, 16 warps (4x4) of 32x64, k32 chunks, 3-stage cp.async.
// smem per stage: Ah[128x40bf16] Al | Bh[256x40] Bl  (pitch 80B, conflict-free:
// row-start bank-quads cycle {0,5,2,7,4,1,6,3}).
// B-fragment ldmatrix double-buffered across the nbp loop.
// ---------------------------------------------------------------------------
__global__ __launch_bounds__(512, 1)
void gemm_kernel(int level) {
    extern __shared__ char smraw[];
    const uint32_t smb = smem_u32(smraw);
    const int tid = threadIdx.x, lane = tid & 31, wid = tid >> 5;
    const int wm = wid >> 2, wn = wid & 3;          // 4 x 4 warps
    const int M = Bd * (128 >> level);
    const int mt = blockIdx.x, bn = blockIdx.y;
    const size_t aRow0 = (size_t)(16384 - (16384 >> level)) + (size_t)mt * 128;
    const size_t bRow0 = (size_t)bn * 256;

    const int lc = tid & 3;          // 16B chunk within k32
    const int lr = tid >> 2;         // 0..127

    float acc[2][8][4];
#pragma unroll
    for (int a = 0; a < 2; a++)
#pragma unroll
        for (int b = 0; b < 8; b++)
#pragma unroll
            for (int c = 0; c < 4; c++) acc[a][b][c] = 0.0f;

    // ldmatrix per-thread base addresses
    const uint32_t aB = smb + (wm * 32 + (lane & 15)) * 80 + (lane >> 4) * 16;
    const uint32_t bB = smb + 20480
                      + (wn * 64 + (lane & 7) + ((lane >> 4) << 3)) * 80
                      + ((lane >> 3) & 1) * 16;

    auto load_stage = [&](int s, int kb) {
        uint32_t st = smb + s * STAGE_BYTES;
        {                                              // A: 128 rows
            size_t go = (aRow0 + lr) * KTOT + kb + lc * 8;
            uint32_t d = st + lr * 80 + lc * 16;
            cpasync16(d,         g_Ah + go);
            cpasync16(d + 10240, g_Al + go);
        }
#pragma unroll
        for (int i = 0; i < 2; i++) {                  // B: 256 rows
            int row = lr + i * 128;
            size_t go = (bRow0 + row) * KTOT + kb + lc * 8;
            uint32_t d = st + 20480 + row * 80 + lc * 16;
            cpasync16(d,         g_Wh + go);
            cpasync16(d + 20480, g_Wl + go);
        }
        asm volatile("cp.async.commit_group;" ::: "memory");
    };

    load_stage(0, 0);
    load_stage(1, 32);

    for (int ks = 0; ks < 64; ks++) {
        asm volatile("cp.async.wait_group 1;" ::: "memory");
        __syncthreads();
        if (ks + 2 < 64) load_stage((ks + 2) % 3, (ks + 2) * 32);
        else asm volatile("cp.async.commit_group;" ::: "memory");

        uint32_t sOff = (uint32_t)(ks % 3) * STAGE_BYTES;
#pragma unroll
        for (int sub = 0; sub < 2; sub++) {
            uint32_t aS = aB + sOff + sub * 32;
            uint32_t bS = bB + sOff + sub * 32;
            uint32_t ah[2][4], al[2][4];
#pragma unroll
            for (int mb = 0; mb < 2; mb++) {
                ldsm4(ah[mb], aS + mb * 1280);
                ldsm4(al[mb], aS + mb * 1280 + 10240);
            }
            // double-buffered B fragments over nbp
            uint32_t bh[2][4], bl[2][4];
            ldsm4(bh[0], bS);
            ldsm4(bl[0], bS + 20480);
#pragma unroll
            for (int nbp = 0; nbp < 4; nbp++) {
                int cur = nbp & 1, nxt = cur ^ 1;
                if (nbp < 3) {
                    ldsm4(bh[nxt], bS + (nbp + 1) * 1280);
                    ldsm4(bl[nxt], bS + (nbp + 1) * 1280 + 20480);
                }
#pragma unroll
                for (int mb = 0; mb < 2; mb++) {
                    mma16816(acc[mb][2*nbp],   ah[mb], bh[cur]);
                    mma16816(acc[mb][2*nbp+1], ah[mb], bh[cur] + 2);
                    mma16816(acc[mb][2*nbp],   al[mb], bh[cur]);
                    mma16816(acc[mb][2*nbp+1], al[mb], bh[cur] + 2);
                    mma16816(acc[mb][2*nbp],   ah[mb], bl[cur]);
                    mma16816(acc[mb][2*nbp+1], ah[mb], bl[cur] + 2);
                }
            }
        }
    }

    // epilogue: direct STG (guarded for M=64 tail level)
    const int gm0 = mt * 128 + wm * 32;
    const int gn0 = bn * 256 + wn * 64;
#pragma unroll
    for (int mb = 0; mb < 2; mb++) {
        int r0 = gm0 + mb * 16 + (lane >> 2);
#pragma unroll
        for (int nb = 0; nb < 8; nb++) {
            int cc = gn0 + nb * 8 + (lane & 3) * 2;
            if (r0 < M) {
                float2 v = make_float2(acc[mb][nb][0], acc[mb][nb][1]);
                *(float2*)(g_pre + (size_t)r0 * NDIM + cc) = v;
            }
            if (r0 + 8 < M) {
                float2 v = make_float2(acc[mb][nb][2], acc[mb][nb][3]);
                *(float2*)(g_pre + (size_t)(r0 + 8) * NDIM + cc) = v;
            }
        }
    }
}

// ---------------------------------------------------------------------------
// Gates: bias + LSTM gate math; writes h (fp32) to d_out, c to ping-pong,
// and h as next-level A rows (bf16 hi/lo).
// ---------------------------------------------------------------------------
__global__ __launch_bounds__(256)
void gates_kernel(float* __restrict__ dout, int level) {
    const int P = 128 >> level;
    const int M = Bd * P;
    int idx = blockIdx.x * 256 + threadIdx.x;
    if (idx >= M * 128) return;
    int m = idx >> 7, u = idx & 127;
    int col0 = u << 3;

    const float* prow = g_pre + (size_t)m * NDIM + col0;
    float pi[8], po[8], pk[8], pl[8], pr[8];
    *(float4*)pi = *(const float4*)(prow);          *(float4*)(pi+4) = *(const float4*)(prow + 4);
    *(float4*)po = *(const float4*)(prow + 1024);   *(float4*)(po+4) = *(const float4*)(prow + 1028);
    *(float4*)pk = *(const float4*)(prow + 2048);   *(float4*)(pk+4) = *(const float4*)(prow + 2052);
    *(float4*)pl = *(const float4*)(prow + 3072);   *(float4*)(pl+4) = *(const float4*)(prow + 3076);
    *(float4*)pr = *(const float4*)(prow + 4096);   *(float4*)(pr+4) = *(const float4*)(prow + 4100);

    const float* bb = g_bcat + col0;
    float bi[8], bo[8], bk[8], bl[8], br[8];
    *(float4*)bi = *(const float4*)(bb);          *(float4*)(bi+4) = *(const float4*)(bb + 4);
    *(float4*)bo = *(const float4*)(bb + 1024);   *(float4*)(bo+4) = *(const float4*)(bb + 1028);
    *(float4*)bk = *(const float4*)(bb + 2048);   *(float4*)(bk+4) = *(const float4*)(bb + 2052);
    *(float4*)bl = *(const float4*)(bb + 3072);   *(float4*)(bl+4) = *(const float4*)(bb + 3076);
    *(float4*)br = *(const float4*)(bb + 4096);   *(float4*)(br+4) = *(const float4*)(bb + 4100);

    float cl[8] = {0,0,0,0,0,0,0,0}, cr[8] = {0,0,0,0,0,0,0,0};
    if (level > 0) {
        const float* cp = g_cbuf[(level + 1) & 1] + (size_t)m * 2048 + col0;
        *(float4*)cl = *(const float4*)(cp);         *(float4*)(cl+4) = *(const float4*)(cp + 4);
        *(float4*)cr = *(const float4*)(cp + 1024);  *(float4*)(cr+4) = *(const float4*)(cp + 1028);
    }

    float cv[8], hv[8];
#pragma unroll
    for (int i = 0; i < 8; i++) {
        float c = sigf(pi[i] + bi[i]) * tanhf_(pk[i] + bk[i])
                + sigf(pl[i] + bl[i]) * cl[i]
                + sigf(pr[i] + br[i]) * cr[i];
        cv[i] = c;
        hv[i] = sigf(po[i] + bo[i]) * tanhf_(c);
    }

    float* cw = g_cbuf[level & 1] + (size_t)m * Hd + col0;
    *(float4*)cw = *(const float4*)cv;  *(float4*)(cw + 4) = *(const float4*)(cv + 4);

    int b = m >> (7 - level);
    int j = m & (P - 1);
    int off = 256 - (256 >> level);
    float* hw = dout + ((size_t)b * FOREST + off + j) * Hd + col0;
    *(float4*)hw = *(const float4*)hv;  *(float4*)(hw + 4) = *(const float4*)(hv + 4);

    if (level < 7) {
        int r = b * (P >> 1) + (j >> 1);
        size_t rowbase = 16384 - (16384 >> (level + 1));
        size_t aoff = (rowbase + r) * (size_t)KTOT + (j & 1) * 1024 + col0;
        uint4 hvv, lvv; cvt8(hv, hvv, lvv);
        *(uint4*)(g_Ah + aoff) = hvv;
        *(uint4*)(g_Al + aoff) = lvv;
    } else {
        float* hroot = dout + (size_t)Bd * FOREST * Hd + (size_t)m * Hd + col0;
        float* croot = hroot + (size_t)Bd * Hd;
        *(float4*)hroot = *(const float4*)hv;  *(float4*)(hroot + 4) = *(const float4*)(hv + 4);
        *(float4*)croot = *(const float4*)cv;  *(float4*)(croot + 4) = *(const float4*)(cv + 4);
    }
}

// ---------------------------------------------------------------------------
// launcher (graph-capturable: kernel launches only, default stream)
// ---------------------------------------------------------------------------
extern "C" void kernel_launch(void* const* d_in, const int* in_sizes, int n_in,
                              void* d_out, int out_size) {
    const int*   tokens = (const int*)  d_in[0];
    const float* emb    = (const float*)d_in[1];
    const float* W_iock = (const float*)d_in[2];
    const float* b_iock = (const float*)d_in[3];
    const float* U_iock = (const float*)d_in[4];
    const float* W_fl   = (const float*)d_in[5];
    const float* b_fl   = (const float*)d_in[6];
    const float* U_fl   = (const float*)d_in[7];
    const float* W_fr   = (const float*)d_in[8];
    const float* b_fr   = (const float*)d_in[9];
    const float* U_fr   = (const float*)d_in[10];
    float* out = (float*)d_out;

    static bool attr_set = false;
    if (!attr_set) {
        cudaFuncSetAttribute(gemm_kernel, cudaFuncAttributeMaxDynamicSharedMemorySize, SMEMT);
        attr_set = true;
    }

    pack_w_kernel<<<dim3(32, 80), 256>>>(W_iock, U_iock, W_fl, U_fl, W_fr, U_fr);
    pack_b_kernel<<<20, 256>>>(b_iock, b_fl, b_fr);
    {
        int total = Bd * 256 * 128;
        embed_kernel<<<(total + 255) / 256, 256>>>(tokens, emb);
    }
    for (int level = 0; level < 8; ++level) {
        int M = Bd * (128 >> level);
        dim3 grid((M + 127) / 128, 20);
        gemm_kernel<<<grid, 512, SMEMT>>>(level);
        int units = M * 128;
        gates_kernel<<<(units + 255) / 256, 256>>>(out, level);
    }
}

// round 9
// speedup vs baseline: 3.4197x; 1.4259x over previous
#include <cuda_runtime.h>
#include <cuda_fp16.h>
#include <cstdint>
#include <math.h>

#define Hd     1024
#define Bd     64
#define NDIM   5120
#define FOREST 255
#define KTOT   2048
#define STAGE_BYTES 40960          // A: 2*10240 (hi+lo), B: 20480
#define NSTAGE 4
#define SMEMT  (NSTAGE * STAGE_BYTES)   // 163840 bytes

// ---------------- static device scratch ----------------
__device__ __half g_Ah[(size_t)16384 * 2048];   // A hi, row-major [row][k]
__device__ __half g_Al[(size_t)16384 * 2048];   // A lo
__device__ __half g_Wh[(size_t)5120 * 2048];    // W^T fp16, [n][k]
__device__ float g_bcat[NDIM];
__device__ float g_pre[(size_t)8192 * NDIM];
__device__ float g_cbuf[2][(size_t)8192 * Hd];

// ---------------- helpers ----------------
__device__ __forceinline__ uint32_t smem_u32(const void* p) {
    uint32_t a;
    asm("{ .reg .u64 t; cvta.to.shared.u64 t, %1; cvt.u32.u64 %0, t; }" : "=r"(a) : "l"(p));
    return a;
}
__device__ __forceinline__ void cpasync16(uint32_t dst, const void* src) {
    asm volatile("cp.async.cg.shared.global [%0], [%1], 16;" :: "r"(dst), "l"(src));
}
__device__ __forceinline__ void ldsm4(uint32_t* r, uint32_t addr) {
    asm volatile("ldmatrix.sync.aligned.m8n8.x4.shared.b16 {%0,%1,%2,%3}, [%4];"
                 : "=r"(r[0]), "=r"(r[1]), "=r"(r[2]), "=r"(r[3]) : "r"(addr));
}
__device__ __forceinline__ void mma16816(float* c, const uint32_t* a, const uint32_t* b) {
    asm volatile("mma.sync.aligned.m16n8k16.row.col.f32.f16.f16.f32 "
                 "{%0,%1,%2,%3}, {%4,%5,%6,%7}, {%8,%9}, {%0,%1,%2,%3};"
                 : "+f"(c[0]), "+f"(c[1]), "+f"(c[2]), "+f"(c[3])
                 : "r"(a[0]), "r"(a[1]), "r"(a[2]), "r"(a[3]), "r"(b[0]), "r"(b[1]));
}
__device__ __forceinline__ uint32_t pk2h(__half a, __half b) {
    __half2 t(a, b);
    return *reinterpret_cast<uint32_t*>(&t);
}
// 8 fp32 -> packed fp16 hi uint4 + lo uint4 (exact residual split)
__device__ __forceinline__ void cvt8h(const float* f, uint4& hv, uint4& lv) {
    uint32_t hw[4], lw[4];
#pragma unroll
    for (int q = 0; q < 4; q++) {
        float a = f[2*q], b = f[2*q+1];
        __half ha = __float2half_rn(a), hb = __float2half_rn(b);
        hw[q] = pk2h(ha, hb);
        lw[q] = pk2h(__float2half_rn(a - __half2float(ha)),
                     __float2half_rn(b - __half2float(hb)));
    }
    hv = make_uint4(hw[0], hw[1], hw[2], hw[3]);
    lv = make_uint4(lw[0], lw[1], lw[2], lw[3]);
}
__device__ __forceinline__ float sigf(float x)   { return 1.0f / (1.0f + __expf(-x)); }
__device__ __forceinline__ float tanhf_(float x) { return 2.0f / (1.0f + __expf(-2.0f * x)) - 1.0f; }

// ---------------------------------------------------------------------------
// Weight pack with smem transpose: g_Wh[n][k] = fp16(cat(W;U)[k][n]).
// ---------------------------------------------------------------------------
__global__ __launch_bounds__(256)
void pack_w_kernel(const float* __restrict__ Wi, const float* __restrict__ Ui,
                   const float* __restrict__ Wfl, const float* __restrict__ Ufl,
                   const float* __restrict__ Wfr, const float* __restrict__ Ufr) {
    __shared__ float ts[64][65];
    int k0 = blockIdx.x * 64, n0 = blockIdx.y * 64;
    const float *Wm, *Um; int st, nc0;
    if (n0 < 3072)      { Wm = Wi;  Um = Ui;  st = 3072; nc0 = n0; }
    else if (n0 < 4096) { Wm = Wfl; Um = Ufl; st = 1024; nc0 = n0 - 3072; }
    else                { Wm = Wfr; Um = Ufr; st = 1024; nc0 = n0 - 4096; }
    const float* base = (k0 < 1024) ? Wm : Um;
    int kr0 = k0 & 1023;
    for (int e = threadIdx.x; e < 4096; e += 256) {
        int r = e >> 6, c = e & 63;
        ts[r][c] = base[(size_t)(kr0 + r) * st + nc0 + c];
    }
    __syncthreads();
    for (int u = threadIdx.x; u < 512; u += 256) {
        int nr = u >> 3, ko = u & 7;
        uint32_t hw[4];
#pragma unroll
        for (int q = 0; q < 4; q++) {
            hw[q] = pk2h(__float2half_rn(ts[ko * 8 + 2*q][nr]),
                         __float2half_rn(ts[ko * 8 + 2*q + 1][nr]));
        }
        size_t off = (size_t)(n0 + nr) * KTOT + k0 + ko * 8;
        *(uint4*)(g_Wh + off) = make_uint4(hw[0], hw[1], hw[2], hw[3]);
    }
}

__global__ void pack_b_kernel(const float* __restrict__ bi,
                              const float* __restrict__ bfl,
                              const float* __restrict__ bfr) {
    int n = blockIdx.x * 256 + threadIdx.x;
    if (n >= NDIM) return;
    g_bcat[n] = (n < 3072) ? bi[n] : (n < 4096) ? bfl[n - 3072] : bfr[n - 4096];
}

// ---------------------------------------------------------------------------
// Embedding: write level-0 A rows (hi/lo fp16). Row r = b*128 + (l>>1),
// k-half = (l&1)*1024.
// ---------------------------------------------------------------------------
__global__ __launch_bounds__(256)
void embed_kernel(const int* __restrict__ tokens, const float* __restrict__ emb) {
    int idx = blockIdx.x * 256 + threadIdx.x;     // B*256*128 units of 8 elems
    if (idx >= Bd * 256 * 128) return;
    int u = idx & 127, t = idx >> 7;
    int b = t >> 8, l = t & 255;
    int tok = tokens[t];
    const float* s = emb + (size_t)tok * Hd + u * 8;
    float f[8];
    *(float4*)f       = *(const float4*)s;
    *(float4*)(f + 4) = *(const float4*)(s + 4);
    uint4 hv, lv; cvt8h(f, hv, lv);
    int r = b * 128 + (l >> 1);
    size_t off = (size_t)r * KTOT + (l & 1) * 1024 + u * 8;
    *(uint4*)(g_Ah + off) = hv;
    *(uint4*)(g_Al + off) = lv;
}

// ---------------------------------------------------------------------------
// HMMA GEMM: pre(M,5120) = A(M,2048) @ W^T.
// fp16 2-pass: D = Ah*Bh + Al*Bh  (A exact in hi+lo, B fp16-quantized).
// CTA 128M x 256N, 16 warps (4x4) of 32x64, k32 chunks, 4-stage cp.async.
// smem per stage: Ah[128x40h] Al | Bh[256x40h]  (pitch 80B, conflict-free:
// row-start bank-quads cycle {0,5,2,7,4,1,6,3}).
// Inner loop: all B frags resident (16 regs), hi pass then lo pass ->
// same-acc HMMA reuse distance = 16 instructions.
// ---------------------------------------------------------------------------
__global__ __launch_bounds__(512, 1)
void gemm_kernel(int level) {
    extern __shared__ char smraw[];
    const uint32_t smb = smem_u32(smraw);
    const int tid = threadIdx.x, lane = tid & 31, wid = tid >> 5;
    const int wm = wid >> 2, wn = wid & 3;          // 4 x 4 warps
    const int M = Bd * (128 >> level);
    const int mt = blockIdx.x, bn = blockIdx.y;
    const size_t aRow0 = (size_t)(16384 - (16384 >> level)) + (size_t)mt * 128;
    const size_t bRow0 = (size_t)bn * 256;

    const int lc = tid & 3;          // 16B chunk within k32
    const int lr = tid >> 2;         // 0..127

    float acc[2][8][4];
#pragma unroll
    for (int a = 0; a < 2; a++)
#pragma unroll
        for (int b = 0; b < 8; b++)
#pragma unroll
            for (int c = 0; c < 4; c++) acc[a][b][c] = 0.0f;

    // ldmatrix per-thread base addresses
    const uint32_t aB = smb + (wm * 32 + (lane & 15)) * 80 + (lane >> 4) * 16;
    const uint32_t bB = smb + 20480
                      + (wn * 64 + (lane & 7) + ((lane >> 4) << 3)) * 80
                      + ((lane >> 3) & 1) * 16;

    auto load_stage = [&](int s, int kb) {
        uint32_t st = smb + s * STAGE_BYTES;
        {                                              // A: 128 rows, hi+lo
            size_t go = (aRow0 + lr) * KTOT + kb + lc * 8;
            uint32_t d = st + lr * 80 + lc * 16;
            cpasync16(d,         g_Ah + go);
            cpasync16(d + 10240, g_Al + go);
        }
#pragma unroll
        for (int i = 0; i < 2; i++) {                  // B: 256 rows
            int row = lr + i * 128;
            size_t go = (bRow0 + row) * KTOT + kb + lc * 8;
            uint32_t d = st + 20480 + row * 80 + lc * 16;
            cpasync16(d, g_Wh + go);
        }
        asm volatile("cp.async.commit_group;" ::: "memory");
    };

    load_stage(0, 0);
    load_stage(1, 32);
    load_stage(2, 64);

    for (int ks = 0; ks < 64; ks++) {
        asm volatile("cp.async.wait_group 2;" ::: "memory");
        __syncthreads();
        if (ks + 3 < 64) load_stage((ks + 3) & 3, (ks + 3) * 32);
        else asm volatile("cp.async.commit_group;" ::: "memory");

        uint32_t sOff = (uint32_t)(ks & 3) * STAGE_BYTES;
#pragma unroll
        for (int sub = 0; sub < 2; sub++) {
            uint32_t aS = aB + sOff + sub * 32;
            uint32_t bS = bB + sOff + sub * 32;
            uint32_t ah[2][4], al[2][4], bf[4][4];
#pragma unroll
            for (int mb = 0; mb < 2; mb++) {
                ldsm4(ah[mb], aS + mb * 1280);
                ldsm4(al[mb], aS + mb * 1280 + 10240);
            }
#pragma unroll
            for (int nbp = 0; nbp < 4; nbp++)
                ldsm4(bf[nbp], bS + nbp * 1280);
            // hi pass
#pragma unroll
            for (int nbp = 0; nbp < 4; nbp++)
#pragma unroll
                for (int mb = 0; mb < 2; mb++) {
                    mma16816(acc[mb][2*nbp],   ah[mb], bf[nbp]);
                    mma16816(acc[mb][2*nbp+1], ah[mb], bf[nbp] + 2);
                }
            // lo pass
#pragma unroll
            for (int nbp = 0; nbp < 4; nbp++)
#pragma unroll
                for (int mb = 0; mb < 2; mb++) {
                    mma16816(acc[mb][2*nbp],   al[mb], bf[nbp]);
                    mma16816(acc[mb][2*nbp+1], al[mb], bf[nbp] + 2);
                }
        }
    }

    // epilogue: direct STG (guarded for M=64 tail level)
    const int gm0 = mt * 128 + wm * 32;
    const int gn0 = bn * 256 + wn * 64;
#pragma unroll
    for (int mb = 0; mb < 2; mb++) {
        int r0 = gm0 + mb * 16 + (lane >> 2);
#pragma unroll
        for (int nb = 0; nb < 8; nb++) {
            int cc = gn0 + nb * 8 + (lane & 3) * 2;
            if (r0 < M) {
                float2 v = make_float2(acc[mb][nb][0], acc[mb][nb][1]);
                *(float2*)(g_pre + (size_t)r0 * NDIM + cc) = v;
            }
            if (r0 + 8 < M) {
                float2 v = make_float2(acc[mb][nb][2], acc[mb][nb][3]);
                *(float2*)(g_pre + (size_t)(r0 + 8) * NDIM + cc) = v;
            }
        }
    }
}

// ---------------------------------------------------------------------------
// Gates: bias + LSTM gate math; writes h (fp32) to d_out, c to ping-pong,
// and h as next-level A rows (fp16 hi/lo).
// ---------------------------------------------------------------------------
__global__ __launch_bounds__(256)
void gates_kernel(float* __restrict__ dout, int level) {
    const int P = 128 >> level;
    const int M = Bd * P;
    int idx = blockIdx.x * 256 + threadIdx.x;
    if (idx >= M * 128) return;
    int m = idx >> 7, u = idx & 127;
    int col0 = u << 3;

    const float* prow = g_pre + (size_t)m * NDIM + col0;
    float pi[8], po[8], pk[8], pl[8], pr[8];
    *(float4*)pi = *(const float4*)(prow);          *(float4*)(pi+4) = *(const float4*)(prow + 4);
    *(float4*)po = *(const float4*)(prow + 1024);   *(float4*)(po+4) = *(const float4*)(prow + 1028);
    *(float4*)pk = *(const float4*)(prow + 2048);   *(float4*)(pk+4) = *(const float4*)(prow + 2052);
    *(float4*)pl = *(const float4*)(prow + 3072);   *(float4*)(pl+4) = *(const float4*)(prow + 3076);
    *(float4*)pr = *(const float4*)(prow + 4096);   *(float4*)(pr+4) = *(const float4*)(prow + 4100);

    const float* bb = g_bcat + col0;
    float bi[8], bo[8], bk[8], bl[8], br[8];
    *(float4*)bi = *(const float4*)(bb);          *(float4*)(bi+4) = *(const float4*)(bb + 4);
    *(float4*)bo = *(const float4*)(bb + 1024);   *(float4*)(bo+4) = *(const float4*)(bb + 1028);
    *(float4*)bk = *(const float4*)(bb + 2048);   *(float4*)(bk+4) = *(const float4*)(bb + 2052);
    *(float4*)bl = *(const float4*)(bb + 3072);   *(float4*)(bl+4) = *(const float4*)(bb + 3076);
    *(float4*)br = *(const float4*)(bb + 4096);   *(float4*)(br+4) = *(const float4*)(bb + 4100);

    float cl[8] = {0,0,0,0,0,0,0,0}, cr[8] = {0,0,0,0,0,0,0,0};
    if (level > 0) {
        const float* cp = g_cbuf[(level + 1) & 1] + (size_t)m * 2048 + col0;
        *(float4*)cl = *(const float4*)(cp);         *(float4*)(cl+4) = *(const float4*)(cp + 4);
        *(float4*)cr = *(const float4*)(cp + 1024);  *(float4*)(cr+4) = *(const float4*)(cp + 1028);
    }

    float cv[8], hv[8];
#pragma unroll
    for (int i = 0; i < 8; i++) {
        float c = sigf(pi[i] + bi[i]) * tanhf_(pk[i] + bk[i])
                + sigf(pl[i] + bl[i]) * cl[i]
                + sigf(pr[i] + br[i]) * cr[i];
        cv[i] = c;
        hv[i] = sigf(po[i] + bo[i]) * tanhf_(c);
    }

    float* cw = g_cbuf[level & 1] + (size_t)m * Hd + col0;
    *(float4*)cw = *(const float4*)cv;  *(float4*)(cw + 4) = *(const float4*)(cv + 4);

    int b = m >> (7 - level);
    int j = m & (P - 1);
    int off = 256 - (256 >> level);
    float* hw = dout + ((size_t)b * FOREST + off + j) * Hd + col0;
    *(float4*)hw = *(const float4*)hv;  *(float4*)(hw + 4) = *(const float4*)(hv + 4);

    if (level < 7) {
        int r = b * (P >> 1) + (j >> 1);
        size_t rowbase = 16384 - (16384 >> (level + 1));
        size_t aoff = (rowbase + r) * (size_t)KTOT + (j & 1) * 1024 + col0;
        uint4 hvv, lvv; cvt8h(hv, hvv, lvv);
        *(uint4*)(g_Ah + aoff) = hvv;
        *(uint4*)(g_Al + aoff) = lvv;
    } else {
        float* hroot = dout + (size_t)Bd * FOREST * Hd + (size_t)m * Hd + col0;
        float* croot = hroot + (size_t)Bd * Hd;
        *(float4*)hroot = *(const float4*)hv;  *(float4*)(hroot + 4) = *(const float4*)(hv + 4);
        *(float4*)croot = *(const float4*)cv;  *(float4*)(croot + 4) = *(const float4*)(cv + 4);
    }
}

// ---------------------------------------------------------------------------
// launcher (graph-capturable: kernel launches only, default stream)
// ---------------------------------------------------------------------------
extern "C" void kernel_launch(void* const* d_in, const int* in_sizes, int n_in,
                              void* d_out, int out_size) {
    const int*   tokens = (const int*)  d_in[0];
    const float* emb    = (const float*)d_in[1];
    const float* W_iock = (const float*)d_in[2];
    const float* b_iock = (const float*)d_in[3];
    const float* U_iock = (const float*)d_in[4];
    const float* W_fl   = (const float*)d_in[5];
    const float* b_fl   = (const float*)d_in[6];
    const float* U_fl   = (const float*)d_in[7];
    const float* W_fr   = (const float*)d_in[8];
    const float* b_fr   = (const float*)d_in[9];
    const float* U_fr   = (const float*)d_in[10];
    float* out = (float*)d_out;

    static bool attr_set = false;
    if (!attr_set) {
        cudaFuncSetAttribute(gemm_kernel, cudaFuncAttributeMaxDynamicSharedMemorySize, SMEMT);
        attr_set = true;
    }

    pack_w_kernel<<<dim3(32, 80), 256>>>(W_iock, U_iock, W_fl, U_fl, W_fr, U_fr);
    pack_b_kernel<<<20, 256>>>(b_iock, b_fl, b_fr);
    {
        int total = Bd * 256 * 128;
        embed_kernel<<<(total + 255) / 256, 256>>>(tokens, emb);
    }
    for (int level = 0; level < 8; ++level) {
        int M = Bd * (128 >> level);
        dim3 grid((M + 127) / 128, 20);
        gemm_kernel<<<grid, 512, SMEMT>>>(level);
        int units = M * 128;
        gates_kernel<<<(units + 255) / 256, 256>>>(out, level);
    }
}

// round 10
// speedup vs baseline: 5.9242x; 1.7324x over previous
#include <cuda_runtime.h>
#include <cuda_fp16.h>
#include <cstdint>
#include <math.h>

#define Hd     1024
#define Bd     64
#define NDIM   5120
#define FOREST 255
#define KTOT   2048
#define PITCH  144                   // 64 fp16 = 128B + 16B pad (conflict-free)
#define STAGE_A (128 * PITCH)        // 18432
#define STAGE_BYTES (384 * PITCH)    // A 128 rows + B 256 rows = 55296
#define NSTAGE 4
#define SMEMT  (NSTAGE * STAGE_BYTES)   // 221184 bytes

// ---------------- static device scratch ----------------
__device__ __half g_Ah[(size_t)16384 * 2048];   // A fp16, row-major [row][k]
__device__ __half g_Wh[(size_t)5120 * 2048];    // W^T fp16, [n][k]
__device__ float g_bcat[NDIM];
__device__ float g_pre[(size_t)8192 * NDIM];
__device__ float g_cbuf[2][(size_t)8192 * Hd];

// ---------------- helpers ----------------
__device__ __forceinline__ uint32_t smem_u32(const void* p) {
    uint32_t a;
    asm("{ .reg .u64 t; cvta.to.shared.u64 t, %1; cvt.u32.u64 %0, t; }" : "=r"(a) : "l"(p));
    return a;
}
__device__ __forceinline__ void cpasync16(uint32_t dst, const void* src) {
    asm volatile("cp.async.cg.shared.global [%0], [%1], 16;" :: "r"(dst), "l"(src));
}
__device__ __forceinline__ void ldsm4(uint32_t* r, uint32_t addr) {
    asm volatile("ldmatrix.sync.aligned.m8n8.x4.shared.b16 {%0,%1,%2,%3}, [%4];"
                 : "=r"(r[0]), "=r"(r[1]), "=r"(r[2]), "=r"(r[3]) : "r"(addr));
}
__device__ __forceinline__ void mma16816(float* c, const uint32_t* a, const uint32_t* b) {
    asm volatile("mma.sync.aligned.m16n8k16.row.col.f32.f16.f16.f32 "
                 "{%0,%1,%2,%3}, {%4,%5,%6,%7}, {%8,%9}, {%0,%1,%2,%3};"
                 : "+f"(c[0]), "+f"(c[1]), "+f"(c[2]), "+f"(c[3])
                 : "r"(a[0]), "r"(a[1]), "r"(a[2]), "r"(a[3]), "r"(b[0]), "r"(b[1]));
}
__device__ __forceinline__ uint32_t pk2h(__half a, __half b) {
    __half2 t(a, b);
    return *reinterpret_cast<uint32_t*>(&t);
}
// 8 fp32 -> packed fp16 uint4
__device__ __forceinline__ uint4 cvt8h(const float* f) {
    uint32_t hw[4];
#pragma unroll
    for (int q = 0; q < 4; q++)
        hw[q] = pk2h(__float2half_rn(f[2*q]), __float2half_rn(f[2*q+1]));
    return make_uint4(hw[0], hw[1], hw[2], hw[3]);
}
__device__ __forceinline__ float sigf(float x)   { return 1.0f / (1.0f + __expf(-x)); }
__device__ __forceinline__ float tanhf_(float x) { return 2.0f / (1.0f + __expf(-2.0f * x)) - 1.0f; }

// ---------------------------------------------------------------------------
// Weight pack with smem transpose: g_Wh[n][k] = fp16(cat(W;U)[k][n]).
// ---------------------------------------------------------------------------
__global__ __launch_bounds__(256)
void pack_w_kernel(const float* __restrict__ Wi, const float* __restrict__ Ui,
                   const float* __restrict__ Wfl, const float* __restrict__ Ufl,
                   const float* __restrict__ Wfr, const float* __restrict__ Ufr) {
    __shared__ float ts[64][65];
    int k0 = blockIdx.x * 64, n0 = blockIdx.y * 64;
    const float *Wm, *Um; int st, nc0;
    if (n0 < 3072)      { Wm = Wi;  Um = Ui;  st = 3072; nc0 = n0; }
    else if (n0 < 4096) { Wm = Wfl; Um = Ufl; st = 1024; nc0 = n0 - 3072; }
    else                { Wm = Wfr; Um = Ufr; st = 1024; nc0 = n0 - 4096; }
    const float* base = (k0 < 1024) ? Wm : Um;
    int kr0 = k0 & 1023;
    for (int e = threadIdx.x; e < 4096; e += 256) {
        int r = e >> 6, c = e & 63;
        ts[r][c] = base[(size_t)(kr0 + r) * st + nc0 + c];
    }
    __syncthreads();
    for (int u = threadIdx.x; u < 512; u += 256) {
        int nr = u >> 3, ko = u & 7;
        float f[8];
#pragma unroll
        for (int i = 0; i < 8; i++) f[i] = ts[ko * 8 + i][nr];
        size_t off = (size_t)(n0 + nr) * KTOT + k0 + ko * 8;
        *(uint4*)(g_Wh + off) = cvt8h(f);
    }
}

__global__ void pack_b_kernel(const float* __restrict__ bi,
                              const float* __restrict__ bfl,
                              const float* __restrict__ bfr) {
    int n = blockIdx.x * 256 + threadIdx.x;
    if (n >= NDIM) return;
    g_bcat[n] = (n < 3072) ? bi[n] : (n < 4096) ? bfl[n - 3072] : bfr[n - 4096];
}

// ---------------------------------------------------------------------------
// Embedding: write level-0 A rows (fp16). Row r = b*128 + (l>>1),
// k-half = (l&1)*1024.
// ---------------------------------------------------------------------------
__global__ __launch_bounds__(256)
void embed_kernel(const int* __restrict__ tokens, const float* __restrict__ emb) {
    int idx = blockIdx.x * 256 + threadIdx.x;     // B*256*128 units of 8 elems
    if (idx >= Bd * 256 * 128) return;
    int u = idx & 127, t = idx >> 7;
    int b = t >> 8, l = t & 255;
    int tok = tokens[t];
    const float* s = emb + (size_t)tok * Hd + u * 8;
    float f[8];
    *(float4*)f       = *(const float4*)s;
    *(float4*)(f + 4) = *(const float4*)(s + 4);
    int r = b * 128 + (l >> 1);
    size_t off = (size_t)r * KTOT + (l & 1) * 1024 + u * 8;
    *(uint4*)(g_Ah + off) = cvt8h(f);
}

// ---------------------------------------------------------------------------
// HMMA GEMM: pre(M,5120) = A(M,2048) @ W^T, single-pass fp16, fp32 acc.
// CTA 128M x 256N, 16 warps (4x4) of 32x64, k64 stages, 4-stage cp.async.
// smem per stage: A[128 x 64h] | B[256 x 64h], pitch 144B (row starts cycle
// all 8 bank-quads -> conflict-free ldmatrix).
// ---------------------------------------------------------------------------
__global__ __launch_bounds__(512, 1)
void gemm_kernel(int level) {
    extern __shared__ char smraw[];
    const uint32_t smb = smem_u32(smraw);
    const int tid = threadIdx.x, lane = tid & 31, wid = tid >> 5;
    const int wm = wid >> 2, wn = wid & 3;          // 4 x 4 warps
    const int M = Bd * (128 >> level);
    const int mt = blockIdx.x, bn = blockIdx.y;
    const size_t aRow0 = (size_t)(16384 - (16384 >> level)) + (size_t)mt * 128;
    const size_t bRow0 = (size_t)bn * 256;

    const int lc = tid & 7;          // 16B chunk within k64 row (8 per row)
    const int lr = tid >> 3;         // 0..63

    float acc[2][8][4];
#pragma unroll
    for (int a = 0; a < 2; a++)
#pragma unroll
        for (int b = 0; b < 8; b++)
#pragma unroll
            for (int c = 0; c < 4; c++) acc[a][b][c] = 0.0f;

    // ldmatrix per-thread base addresses
    const uint32_t aB = smb + (wm * 32 + (lane & 15)) * PITCH + (lane >> 4) * 16;
    const uint32_t bB = smb + STAGE_A
                      + (wn * 64 + (lane & 7) + ((lane >> 4) << 3)) * PITCH
                      + ((lane >> 3) & 1) * 16;

    auto load_stage = [&](int s, int kb) {
        uint32_t st = smb + s * STAGE_BYTES;
#pragma unroll
        for (int i = 0; i < 2; i++) {                  // A: 128 rows
            int row = lr + i * 64;
            size_t go = (aRow0 + row) * KTOT + kb + lc * 8;
            cpasync16(st + row * PITCH + lc * 16, g_Ah + go);
        }
#pragma unroll
        for (int i = 0; i < 4; i++) {                  // B: 256 rows
            int row = lr + i * 64;
            size_t go = (bRow0 + row) * KTOT + kb + lc * 8;
            cpasync16(st + STAGE_A + row * PITCH + lc * 16, g_Wh + go);
        }
        asm volatile("cp.async.commit_group;" ::: "memory");
    };

    load_stage(0, 0);
    load_stage(1, 64);
    load_stage(2, 128);

    for (int ks = 0; ks < 32; ks++) {
        asm volatile("cp.async.wait_group 2;" ::: "memory");
        __syncthreads();
        if (ks + 3 < 32) load_stage((ks + 3) & 3, (ks + 3) * 64);
        else asm volatile("cp.async.commit_group;" ::: "memory");

        uint32_t sOff = (uint32_t)(ks & 3) * STAGE_BYTES;
#pragma unroll
        for (int sub = 0; sub < 4; sub++) {
            uint32_t aS = aB + sOff + sub * 32;
            uint32_t bS = bB + sOff + sub * 32;
            uint32_t ah[2][4], bf[4][4];
            ldsm4(ah[0], aS);
            ldsm4(ah[1], aS + 16 * PITCH);
#pragma unroll
            for (int nbp = 0; nbp < 4; nbp++)
                ldsm4(bf[nbp], bS + nbp * 16 * PITCH);
#pragma unroll
            for (int nbp = 0; nbp < 4; nbp++)
#pragma unroll
                for (int mb = 0; mb < 2; mb++) {
                    mma16816(acc[mb][2*nbp],   ah[mb], bf[nbp]);
                    mma16816(acc[mb][2*nbp+1], ah[mb], bf[nbp] + 2);
                }
        }
    }

    // epilogue: direct STG (guarded for M=64 tail level)
    const int gm0 = mt * 128 + wm * 32;
    const int gn0 = bn * 256 + wn * 64;
#pragma unroll
    for (int mb = 0; mb < 2; mb++) {
        int r0 = gm0 + mb * 16 + (lane >> 2);
#pragma unroll
        for (int nb = 0; nb < 8; nb++) {
            int cc = gn0 + nb * 8 + (lane & 3) * 2;
            if (r0 < M) {
                float2 v = make_float2(acc[mb][nb][0], acc[mb][nb][1]);
                *(float2*)(g_pre + (size_t)r0 * NDIM + cc) = v;
            }
            if (r0 + 8 < M) {
                float2 v = make_float2(acc[mb][nb][2], acc[mb][nb][3]);
                *(float2*)(g_pre + (size_t)(r0 + 8) * NDIM + cc) = v;
            }
        }
    }
}

// ---------------------------------------------------------------------------
// Gates: bias + LSTM gate math; writes h (fp32) to d_out, c to ping-pong,
// and h as next-level A rows (fp16).
// ---------------------------------------------------------------------------
__global__ __launch_bounds__(256)
void gates_kernel(float* __restrict__ dout, int level) {
    const int P = 128 >> level;
    const int M = Bd * P;
    int idx = blockIdx.x * 256 + threadIdx.x;
    if (idx >= M * 128) return;
    int m = idx >> 7, u = idx & 127;
    int col0 = u << 3;

    const float* prow = g_pre + (size_t)m * NDIM + col0;
    float pi[8], po[8], pk[8], pl[8], pr[8];
    *(float4*)pi = *(const float4*)(prow);          *(float4*)(pi+4) = *(const float4*)(prow + 4);
    *(float4*)po = *(const float4*)(prow + 1024);   *(float4*)(po+4) = *(const float4*)(prow + 1028);
    *(float4*)pk = *(const float4*)(prow + 2048);   *(float4*)(pk+4) = *(const float4*)(prow + 2052);
    *(float4*)pl = *(const float4*)(prow + 3072);   *(float4*)(pl+4) = *(const float4*)(prow + 3076);
    *(float4*)pr = *(const float4*)(prow + 4096);   *(float4*)(pr+4) = *(const float4*)(prow + 4100);

    const float* bb = g_bcat + col0;
    float bi[8], bo[8], bk[8], bl[8], br[8];
    *(float4*)bi = *(const float4*)(bb);          *(float4*)(bi+4) = *(const float4*)(bb + 4);
    *(float4*)bo = *(const float4*)(bb + 1024);   *(float4*)(bo+4) = *(const float4*)(bb + 1028);
    *(float4*)bk = *(const float4*)(bb + 2048);   *(float4*)(bk+4) = *(const float4*)(bb + 2052);
    *(float4*)bl = *(const float4*)(bb + 3072);   *(float4*)(bl+4) = *(const float4*)(bb + 3076);
    *(float4*)br = *(const float4*)(bb + 4096);   *(float4*)(br+4) = *(const float4*)(bb + 4100);

    float cl[8] = {0,0,0,0,0,0,0,0}, cr[8] = {0,0,0,0,0,0,0,0};
    if (level > 0) {
        const float* cp = g_cbuf[(level + 1) & 1] + (size_t)m * 2048 + col0;
        *(float4*)cl = *(const float4*)(cp);         *(float4*)(cl+4) = *(const float4*)(cp + 4);
        *(float4*)cr = *(const float4*)(cp + 1024);  *(float4*)(cr+4) = *(const float4*)(cp + 1028);
    }

    float cv[8], hv[8];
#pragma unroll
    for (int i = 0; i < 8; i++) {
        float c = sigf(pi[i] + bi[i]) * tanhf_(pk[i] + bk[i])
                + sigf(pl[i] + bl[i]) * cl[i]
                + sigf(pr[i] + br[i]) * cr[i];
        cv[i] = c;
        hv[i] = sigf(po[i] + bo[i]) * tanhf_(c);
    }

    float* cw = g_cbuf[level & 1] + (size_t)m * Hd + col0;
    *(float4*)cw = *(const float4*)cv;  *(float4*)(cw + 4) = *(const float4*)(cv + 4);

    int b = m >> (7 - level);
    int j = m & (P - 1);
    int off = 256 - (256 >> level);
    float* hw = dout + ((size_t)b * FOREST + off + j) * Hd + col0;
    *(float4*)hw = *(const float4*)hv;  *(float4*)(hw + 4) = *(const float4*)(hv + 4);

    if (level < 7) {
        int r = b * (P >> 1) + (j >> 1);
        size_t rowbase = 16384 - (16384 >> (level + 1));
        size_t aoff = (rowbase + r) * (size_t)KTOT + (j & 1) * 1024 + col0;
        *(uint4*)(g_Ah + aoff) = cvt8h(hv);
    } else {
        float* hroot = dout + (size_t)Bd * FOREST * Hd + (size_t)m * Hd + col0;
        float* croot = hroot + (size_t)Bd * Hd;
        *(float4*)hroot = *(const float4*)hv;  *(float4*)(hroot + 4) = *(const float4*)(hv + 4);
        *(float4*)croot = *(const float4*)cv;  *(float4*)(croot + 4) = *(const float4*)(cv + 4);
    }
}

// ---------------------------------------------------------------------------
// launcher (graph-capturable: kernel launches only, default stream)
// ---------------------------------------------------------------------------
extern "C" void kernel_launch(void* const* d_in, const int* in_sizes, int n_in,
                              void* d_out, int out_size) {
    const int*   tokens = (const int*)  d_in[0];
    const float* emb    = (const float*)d_in[1];
    const float* W_iock = (const float*)d_in[2];
    const float* b_iock = (const float*)d_in[3];
    const float* U_iock = (const float*)d_in[4];
    const float* W_fl   = (const float*)d_in[5];
    const float* b_fl   = (const float*)d_in[6];
    const float* U_fl   = (const float*)d_in[7];
    const float* W_fr   = (const float*)d_in[8];
    const float* b_fr   = (const float*)d_in[9];
    const float* U_fr   = (const float*)d_in[10];
    float* out = (float*)d_out;

    static bool attr_set = false;
    if (!attr_set) {
        cudaFuncSetAttribute(gemm_kernel, cudaFuncAttributeMaxDynamicSharedMemorySize, SMEMT);
        attr_set = true;
    }

    pack_w_kernel<<<dim3(32, 80), 256>>>(W_iock, U_iock, W_fl, U_fl, W_fr, U_fr);
    pack_b_kernel<<<20, 256>>>(b_iock, b_fl, b_fr);
    {
        int total = Bd * 256 * 128;
        embed_kernel<<<(total + 255) / 256, 256>>>(tokens, emb);
    }
    for (int level = 0; level < 8; ++level) {
        int M = Bd * (128 >> level);
        dim3 grid((M + 127) / 128, 20);
        gemm_kernel<<<grid, 512, SMEMT>>>(level);
        int units = M * 128;
        gates_kernel<<<(units + 255) / 256, 256>>>(out, level);
    }
}

// round 11
// speedup vs baseline: 6.8856x; 1.1623x over previous
#include <cuda_runtime.h>
#include <cuda_fp16.h>
#include <cstdint>
#include <math.h>

#define Hd     1024
#define Bd     64
#define NDIM   5120
#define FOREST 255
#define KTOT   2048
#define PITCH  144                   // 64 fp16 = 128B + 16B pad (conflict-free)
#define STAGE_A (128 * PITCH)        // 18432
#define STAGE_BYTES (256 * PITCH)    // A 128 rows + B 128 rows = 36864
#define NSTAGE 3
#define SMEMT  (NSTAGE * STAGE_BYTES)   // 110592 bytes -> 2 CTAs/SM

// ---------------- static device scratch ----------------
__device__ __half g_Ah[(size_t)16384 * 2048];   // A fp16, row-major [row][k]
__device__ __half g_Wh[(size_t)5120 * 2048];    // W^T fp16, [n][k]
__device__ float g_bcat[NDIM];
__device__ float g_pre[(size_t)8192 * NDIM];
__device__ float g_cbuf[2][(size_t)8192 * Hd];

// ---------------- helpers ----------------
__device__ __forceinline__ uint32_t smem_u32(const void* p) {
    uint32_t a;
    asm("{ .reg .u64 t; cvta.to.shared.u64 t, %1; cvt.u32.u64 %0, t; }" : "=r"(a) : "l"(p));
    return a;
}
__device__ __forceinline__ void cpasync16(uint32_t dst, const void* src) {
    asm volatile("cp.async.cg.shared.global [%0], [%1], 16;" :: "r"(dst), "l"(src));
}
__device__ __forceinline__ void ldsm4(uint32_t* r, uint32_t addr) {
    asm volatile("ldmatrix.sync.aligned.m8n8.x4.shared.b16 {%0,%1,%2,%3}, [%4];"
                 : "=r"(r[0]), "=r"(r[1]), "=r"(r[2]), "=r"(r[3]) : "r"(addr));
}
__device__ __forceinline__ void mma16816(float* c, const uint32_t* a, const uint32_t* b) {
    asm volatile("mma.sync.aligned.m16n8k16.row.col.f32.f16.f16.f32 "
                 "{%0,%1,%2,%3}, {%4,%5,%6,%7}, {%8,%9}, {%0,%1,%2,%3};"
                 : "+f"(c[0]), "+f"(c[1]), "+f"(c[2]), "+f"(c[3])
                 : "r"(a[0]), "r"(a[1]), "r"(a[2]), "r"(a[3]), "r"(b[0]), "r"(b[1]));
}
__device__ __forceinline__ uint32_t pk2h(__half a, __half b) {
    __half2 t(a, b);
    return *reinterpret_cast<uint32_t*>(&t);
}
// 8 fp32 -> packed fp16 uint4
__device__ __forceinline__ uint4 cvt8h(const float* f) {
    uint32_t hw[4];
#pragma unroll
    for (int q = 0; q < 4; q++)
        hw[q] = pk2h(__float2half_rn(f[2*q]), __float2half_rn(f[2*q+1]));
    return make_uint4(hw[0], hw[1], hw[2], hw[3]);
}
__device__ __forceinline__ float sigf(float x)   { return 1.0f / (1.0f + __expf(-x)); }
__device__ __forceinline__ float tanhf_(float x) { return 2.0f / (1.0f + __expf(-2.0f * x)) - 1.0f; }

// ---------------------------------------------------------------------------
// Weight pack with smem transpose: g_Wh[n][k] = fp16(cat(W;U)[k][n]).
// ---------------------------------------------------------------------------
__global__ __launch_bounds__(256)
void pack_w_kernel(const float* __restrict__ Wi, const float* __restrict__ Ui,
                   const float* __restrict__ Wfl, const float* __restrict__ Ufl,
                   const float* __restrict__ Wfr, const float* __restrict__ Ufr) {
    __shared__ float ts[64][65];
    int k0 = blockIdx.x * 64, n0 = blockIdx.y * 64;
    const float *Wm, *Um; int st, nc0;
    if (n0 < 3072)      { Wm = Wi;  Um = Ui;  st = 3072; nc0 = n0; }
    else if (n0 < 4096) { Wm = Wfl; Um = Ufl; st = 1024; nc0 = n0 - 3072; }
    else                { Wm = Wfr; Um = Ufr; st = 1024; nc0 = n0 - 4096; }
    const float* base = (k0 < 1024) ? Wm : Um;
    int kr0 = k0 & 1023;
    for (int e = threadIdx.x; e < 4096; e += 256) {
        int r = e >> 6, c = e & 63;
        ts[r][c] = base[(size_t)(kr0 + r) * st + nc0 + c];
    }
    __syncthreads();
    for (int u = threadIdx.x; u < 512; u += 256) {
        int nr = u >> 3, ko = u & 7;
        float f[8];
#pragma unroll
        for (int i = 0; i < 8; i++) f[i] = ts[ko * 8 + i][nr];
        size_t off = (size_t)(n0 + nr) * KTOT + k0 + ko * 8;
        *(uint4*)(g_Wh + off) = cvt8h(f);
    }
}

__global__ void pack_b_kernel(const float* __restrict__ bi,
                              const float* __restrict__ bfl,
                              const float* __restrict__ bfr) {
    int n = blockIdx.x * 256 + threadIdx.x;
    if (n >= NDIM) return;
    g_bcat[n] = (n < 3072) ? bi[n] : (n < 4096) ? bfl[n - 3072] : bfr[n - 4096];
}

// ---------------------------------------------------------------------------
// Embedding: write level-0 A rows (fp16). Row r = b*128 + (l>>1),
// k-half = (l&1)*1024.
// ---------------------------------------------------------------------------
__global__ __launch_bounds__(256)
void embed_kernel(const int* __restrict__ tokens, const float* __restrict__ emb) {
    int idx = blockIdx.x * 256 + threadIdx.x;     // B*256*128 units of 8 elems
    if (idx >= Bd * 256 * 128) return;
    int u = idx & 127, t = idx >> 7;
    int b = t >> 8, l = t & 255;
    int tok = tokens[t];
    const float* s = emb + (size_t)tok * Hd + u * 8;
    float f[8];
    *(float4*)f       = *(const float4*)s;
    *(float4*)(f + 4) = *(const float4*)(s + 4);
    int r = b * 128 + (l >> 1);
    size_t off = (size_t)r * KTOT + (l & 1) * 1024 + u * 8;
    *(uint4*)(g_Ah + off) = cvt8h(f);
}

// ---------------------------------------------------------------------------
// HMMA GEMM: pre(M,5120) = A(M,2048) @ W^T, single-pass fp16, fp32 acc.
// CTA 128M x 128N, 8 warps (4x2) of 32x64, k64 stages, 3-stage cp.async,
// 110.6 KB smem -> 2 CTAs/SM so barrier bubbles of one CTA are hidden by
// the other. Pitch 144B (row starts cycle all 8 bank-quads, conflict-free).
// ---------------------------------------------------------------------------
__global__ __launch_bounds__(256, 2)
void gemm_kernel(int level) {
    extern __shared__ char smraw[];
    const uint32_t smb = smem_u32(smraw);
    const int tid = threadIdx.x, lane = tid & 31, wid = tid >> 5;
    const int wm = wid >> 1, wn = wid & 1;          // 4 x 2 warps
    const int M = Bd * (128 >> level);
    const int mt = blockIdx.x, bn = blockIdx.y;
    const size_t aRow0 = (size_t)(16384 - (16384 >> level)) + (size_t)mt * 128;
    const size_t bRow0 = (size_t)bn * 128;

    const int lc = tid & 7;          // 16B chunk within k64 row (8 per row)
    const int lr = tid >> 3;         // 0..31

    float acc[2][8][4];
#pragma unroll
    for (int a = 0; a < 2; a++)
#pragma unroll
        for (int b = 0; b < 8; b++)
#pragma unroll
            for (int c = 0; c < 4; c++) acc[a][b][c] = 0.0f;

    // ldmatrix per-thread base addresses
    const uint32_t aB = smb + (wm * 32 + (lane & 15)) * PITCH + (lane >> 4) * 16;
    const uint32_t bB = smb + STAGE_A
                      + (wn * 64 + (lane & 7) + ((lane >> 4) << 3)) * PITCH
                      + ((lane >> 3) & 1) * 16;

    auto load_stage = [&](int s, int kb) {
        uint32_t st = smb + s * STAGE_BYTES;
#pragma unroll
        for (int i = 0; i < 4; i++) {                  // A: 128 rows
            int row = lr + i * 32;
            size_t go = (aRow0 + row) * KTOT + kb + lc * 8;
            cpasync16(st + row * PITCH + lc * 16, g_Ah + go);
        }
#pragma unroll
        for (int i = 0; i < 4; i++) {                  // B: 128 rows
            int row = lr + i * 32;
            size_t go = (bRow0 + row) * KTOT + kb + lc * 8;
            cpasync16(st + STAGE_A + row * PITCH + lc * 16, g_Wh + go);
        }
        asm volatile("cp.async.commit_group;" ::: "memory");
    };

    load_stage(0, 0);
    load_stage(1, 64);

    for (int ks = 0; ks < 32; ks++) {
        asm volatile("cp.async.wait_group 1;" ::: "memory");
        __syncthreads();
        if (ks + 2 < 32) load_stage((ks + 2) % 3, (ks + 2) * 64);
        else asm volatile("cp.async.commit_group;" ::: "memory");

        uint32_t sOff = (uint32_t)(ks % 3) * STAGE_BYTES;
#pragma unroll
        for (int sub = 0; sub < 4; sub++) {
            uint32_t aS = aB + sOff + sub * 32;
            uint32_t bS = bB + sOff + sub * 32;
            uint32_t ah[2][4], bf[4][4];
            ldsm4(ah[0], aS);
            ldsm4(ah[1], aS + 16 * PITCH);
#pragma unroll
            for (int nbp = 0; nbp < 4; nbp++)
                ldsm4(bf[nbp], bS + nbp * 16 * PITCH);
#pragma unroll
            for (int nbp = 0; nbp < 4; nbp++)
#pragma unroll
                for (int mb = 0; mb < 2; mb++) {
                    mma16816(acc[mb][2*nbp],   ah[mb], bf[nbp]);
                    mma16816(acc[mb][2*nbp+1], ah[mb], bf[nbp] + 2);
                }
        }
    }

    // epilogue: direct STG (guarded for M=64 tail level)
    const int gm0 = mt * 128 + wm * 32;
    const int gn0 = bn * 128 + wn * 64;
#pragma unroll
    for (int mb = 0; mb < 2; mb++) {
        int r0 = gm0 + mb * 16 + (lane >> 2);
#pragma unroll
        for (int nb = 0; nb < 8; nb++) {
            int cc = gn0 + nb * 8 + (lane & 3) * 2;
            if (r0 < M) {
                float2 v = make_float2(acc[mb][nb][0], acc[mb][nb][1]);
                *(float2*)(g_pre + (size_t)r0 * NDIM + cc) = v;
            }
            if (r0 + 8 < M) {
                float2 v = make_float2(acc[mb][nb][2], acc[mb][nb][3]);
                *(float2*)(g_pre + (size_t)(r0 + 8) * NDIM + cc) = v;
            }
        }
    }
}

// ---------------------------------------------------------------------------
// Gates: bias + LSTM gate math; writes h (fp32) to d_out, c to ping-pong,
// and h as next-level A rows (fp16).
// ---------------------------------------------------------------------------
__global__ __launch_bounds__(256)
void gates_kernel(float* __restrict__ dout, int level) {
    const int P = 128 >> level;
    const int M = Bd * P;
    int idx = blockIdx.x * 256 + threadIdx.x;
    if (idx >= M * 128) return;
    int m = idx >> 7, u = idx & 127;
    int col0 = u << 3;

    const float* prow = g_pre + (size_t)m * NDIM + col0;
    float pi[8], po[8], pk[8], pl[8], pr[8];
    *(float4*)pi = *(const float4*)(prow);          *(float4*)(pi+4) = *(const float4*)(prow + 4);
    *(float4*)po = *(const float4*)(prow + 1024);   *(float4*)(po+4) = *(const float4*)(prow + 1028);
    *(float4*)pk = *(const float4*)(prow + 2048);   *(float4*)(pk+4) = *(const float4*)(prow + 2052);
    *(float4*)pl = *(const float4*)(prow + 3072);   *(float4*)(pl+4) = *(const float4*)(prow + 3076);
    *(float4*)pr = *(const float4*)(prow + 4096);   *(float4*)(pr+4) = *(const float4*)(prow + 4100);

    const float* bb = g_bcat + col0;
    float bi[8], bo[8], bk[8], bl[8], br[8];
    *(float4*)bi = *(const float4*)(bb);          *(float4*)(bi+4) = *(const float4*)(bb + 4);
    *(float4*)bo = *(const float4*)(bb + 1024);   *(float4*)(bo+4) = *(const float4*)(bb + 1028);
    *(float4*)bk = *(const float4*)(bb + 2048);   *(float4*)(bk+4) = *(const float4*)(bb + 2052);
    *(float4*)bl = *(const float4*)(bb + 3072);   *(float4*)(bl+4) = *(const float4*)(bb + 3076);
    *(float4*)br = *(const float4*)(bb + 4096);   *(float4*)(br+4) = *(const float4*)(bb + 4100);

    float cl[8] = {0,0,0,0,0,0,0,0}, cr[8] = {0,0,0,0,0,0,0,0};
    if (level > 0) {
        const float* cp = g_cbuf[(level + 1) & 1] + (size_t)m * 2048 + col0;
        *(float4*)cl = *(const float4*)(cp);         *(float4*)(cl+4) = *(const float4*)(cp + 4);
        *(float4*)cr = *(const float4*)(cp + 1024);  *(float4*)(cr+4) = *(const float4*)(cp + 1028);
    }

    float cv[8], hv[8];
#pragma unroll
    for (int i = 0; i < 8; i++) {
        float c = sigf(pi[i] + bi[i]) * tanhf_(pk[i] + bk[i])
                + sigf(pl[i] + bl[i]) * cl[i]
                + sigf(pr[i] + br[i]) * cr[i];
        cv[i] = c;
        hv[i] = sigf(po[i] + bo[i]) * tanhf_(c);
    }

    float* cw = g_cbuf[level & 1] + (size_t)m * Hd + col0;
    *(float4*)cw = *(const float4*)cv;  *(float4*)(cw + 4) = *(const float4*)(cv + 4);

    int b = m >> (7 - level);
    int j = m & (P - 1);
    int off = 256 - (256 >> level);
    float* hw = dout + ((size_t)b * FOREST + off + j) * Hd + col0;
    *(float4*)hw = *(const float4*)hv;  *(float4*)(hw + 4) = *(const float4*)(hv + 4);

    if (level < 7) {
        int r = b * (P >> 1) + (j >> 1);
        size_t rowbase = 16384 - (16384 >> (level + 1));
        size_t aoff = (rowbase + r) * (size_t)KTOT + (j & 1) * 1024 + col0;
        *(uint4*)(g_Ah + aoff) = cvt8h(hv);
    } else {
        float* hroot = dout + (size_t)Bd * FOREST * Hd + (size_t)m * Hd + col0;
        float* croot = hroot + (size_t)Bd * Hd;
        *(float4*)hroot = *(const float4*)hv;  *(float4*)(hroot + 4) = *(const float4*)(hv + 4);
        *(float4*)croot = *(const float4*)cv;  *(float4*)(croot + 4) = *(const float4*)(cv + 4);
    }
}

// ---------------------------------------------------------------------------
// launcher (graph-capturable: kernel launches only, default stream)
// ---------------------------------------------------------------------------
extern "C" void kernel_launch(void* const* d_in, const int* in_sizes, int n_in,
                              void* d_out, int out_size) {
    const int*   tokens = (const int*)  d_in[0];
    const float* emb    = (const float*)d_in[1];
    const float* W_iock = (const float*)d_in[2];
    const float* b_iock = (const float*)d_in[3];
    const float* U_iock = (const float*)d_in[4];
    const float* W_fl   = (const float*)d_in[5];
    const float* b_fl   = (const float*)d_in[6];
    const float* U_fl   = (const float*)d_in[7];
    const float* W_fr   = (const float*)d_in[8];
    const float* b_fr   = (const float*)d_in[9];
    const float* U_fr   = (const float*)d_in[10];
    float* out = (float*)d_out;

    static bool attr_set = false;
    if (!attr_set) {
        cudaFuncSetAttribute(gemm_kernel, cudaFuncAttributeMaxDynamicSharedMemorySize, SMEMT);
        attr_set = true;
    }

    pack_w_kernel<<<dim3(32, 80), 256>>>(W_iock, U_iock, W_fl, U_fl, W_fr, U_fr);
    pack_b_kernel<<<20, 256>>>(b_iock, b_fl, b_fr);
    {
        int total = Bd * 256 * 128;
        embed_kernel<<<(total + 255) / 256, 256>>>(tokens, emb);
    }
    for (int level = 0; level < 8; ++level) {
        int M = Bd * (128 >> level);
        dim3 grid((M + 127) / 128, 40);
        gemm_kernel<<<grid, 256, SMEMT>>>(level);
        int units = M * 128;
        gates_kernel<<<(units + 255) / 256, 256>>>(out, level);
    }
}

// round 12
// speedup vs baseline: 8.3139x; 1.2074x over previous
#include <cuda_runtime.h>
#include <cuda_fp16.h>
#include <cstdint>
#include <math.h>

#define Hd     1024
#define Bd     64
#define NDIM   5120
#define FOREST 255
#define KTOT   2048
#define PITCH  144                   // 64 fp16 = 128B + 16B pad (conflict-free)
#define STAGE_A (128 * PITCH)        // 18432
#define STAGE_BYTES (256 * PITCH)    // A 128 rows + B 128 rows = 36864
#define NSTAGE 5
#define SMEM_BARS 1024
#define SMEMT  (SMEM_BARS + NSTAGE * STAGE_BYTES)   // 185344 bytes

// ---------------- static device scratch ----------------
__device__ __half g_Ah[(size_t)16384 * 2048];   // A fp16, row-major [row][k]
__device__ __half g_Wh[(size_t)5120 * 2048];    // W^T fp16, [n][k]
__device__ float g_bcat[NDIM];
__device__ float g_pre[(size_t)8192 * NDIM];
__device__ float g_cbuf[2][(size_t)8192 * Hd];

// ---------------- helpers ----------------
__device__ __forceinline__ uint32_t smem_u32(const void* p) {
    uint32_t a;
    asm("{ .reg .u64 t; cvta.to.shared.u64 t, %1; cvt.u32.u64 %0, t; }" : "=r"(a) : "l"(p));
    return a;
}
__device__ __forceinline__ void cpasync16(uint32_t dst, const void* src) {
    asm volatile("cp.async.cg.shared.global [%0], [%1], 16;" :: "r"(dst), "l"(src));
}
__device__ __forceinline__ void mbar_init(uint32_t a, uint32_t c) {
    asm volatile("mbarrier.init.shared.b64 [%0], %1;" :: "r"(a), "r"(c) : "memory");
}
__device__ __forceinline__ void mbar_arrive(uint32_t a) {
    asm volatile("mbarrier.arrive.shared.b64 _, [%0];" :: "r"(a) : "memory");
}
// arrive on mbarrier when this thread's prior cp.asyncs complete (count pre-set)
__device__ __forceinline__ void cpasync_mbar_arrive(uint32_t a) {
    asm volatile("cp.async.mbarrier.arrive.noinc.shared.b64 [%0];" :: "r"(a) : "memory");
}
__device__ __forceinline__ void mbar_wait(uint32_t mbar, int phase) {
    asm volatile(
        "{\n\t.reg .pred P1;\n\t"
        "W_%=:\n\t"
        "mbarrier.try_wait.parity.acquire.cta.shared::cta.b64 P1, [%0], %1, 0x989680;\n\t"
        "@P1 bra.uni D_%=;\n\t"
        "bra.uni W_%=;\n\t"
        "D_%=:\n\t}"
        :: "r"(mbar), "r"(phase) : "memory");
}
__device__ __forceinline__ void ldsm4(uint32_t* r, uint32_t addr) {
    asm volatile("ldmatrix.sync.aligned.m8n8.x4.shared.b16 {%0,%1,%2,%3}, [%4];"
                 : "=r"(r[0]), "=r"(r[1]), "=r"(r[2]), "=r"(r[3]) : "r"(addr));
}
__device__ __forceinline__ void mma16816(float* c, const uint32_t* a, const uint32_t* b) {
    asm volatile("mma.sync.aligned.m16n8k16.row.col.f32.f16.f16.f32 "
                 "{%0,%1,%2,%3}, {%4,%5,%6,%7}, {%8,%9}, {%0,%1,%2,%3};"
                 : "+f"(c[0]), "+f"(c[1]), "+f"(c[2]), "+f"(c[3])
                 : "r"(a[0]), "r"(a[1]), "r"(a[2]), "r"(a[3]), "r"(b[0]), "r"(b[1]));
}
__device__ __forceinline__ uint32_t pk2h(__half a, __half b) {
    __half2 t(a, b);
    return *reinterpret_cast<uint32_t*>(&t);
}
// 8 fp32 -> packed fp16 uint4
__device__ __forceinline__ uint4 cvt8h(const float* f) {
    uint32_t hw[4];
#pragma unroll
    for (int q = 0; q < 4; q++)
        hw[q] = pk2h(__float2half_rn(f[2*q]), __float2half_rn(f[2*q+1]));
    return make_uint4(hw[0], hw[1], hw[2], hw[3]);
}
__device__ __forceinline__ float sigf(float x)   { return 1.0f / (1.0f + __expf(-x)); }
__device__ __forceinline__ float tanhf_(float x) { return 2.0f / (1.0f + __expf(-2.0f * x)) - 1.0f; }

// ---------------------------------------------------------------------------
// Weight pack with smem transpose: g_Wh[n][k] = fp16(cat(W;U)[k][n]).
// ---------------------------------------------------------------------------
__global__ __launch_bounds__(256)
void pack_w_kernel(const float* __restrict__ Wi, const float* __restrict__ Ui,
                   const float* __restrict__ Wfl, const float* __restrict__ Ufl,
                   const float* __restrict__ Wfr, const float* __restrict__ Ufr) {
    __shared__ float ts[64][65];
    int k0 = blockIdx.x * 64, n0 = blockIdx.y * 64;
    const float *Wm, *Um; int st, nc0;
    if (n0 < 3072)      { Wm = Wi;  Um = Ui;  st = 3072; nc0 = n0; }
    else if (n0 < 4096) { Wm = Wfl; Um = Ufl; st = 1024; nc0 = n0 - 3072; }
    else                { Wm = Wfr; Um = Ufr; st = 1024; nc0 = n0 - 4096; }
    const float* base = (k0 < 1024) ? Wm : Um;
    int kr0 = k0 & 1023;
    for (int e = threadIdx.x; e < 4096; e += 256) {
        int r = e >> 6, c = e & 63;
        ts[r][c] = base[(size_t)(kr0 + r) * st + nc0 + c];
    }
    __syncthreads();
    for (int u = threadIdx.x; u < 512; u += 256) {
        int nr = u >> 3, ko = u & 7;
        float f[8];
#pragma unroll
        for (int i = 0; i < 8; i++) f[i] = ts[ko * 8 + i][nr];
        size_t off = (size_t)(n0 + nr) * KTOT + k0 + ko * 8;
        *(uint4*)(g_Wh + off) = cvt8h(f);
    }
}

__global__ void pack_b_kernel(const float* __restrict__ bi,
                              const float* __restrict__ bfl,
                              const float* __restrict__ bfr) {
    int n = blockIdx.x * 256 + threadIdx.x;
    if (n >= NDIM) return;
    g_bcat[n] = (n < 3072) ? bi[n] : (n < 4096) ? bfl[n - 3072] : bfr[n - 4096];
}

// ---------------------------------------------------------------------------
// Embedding: write level-0 A rows (fp16). Row r = b*128 + (l>>1),
// k-half = (l&1)*1024.
// ---------------------------------------------------------------------------
__global__ __launch_bounds__(256)
void embed_kernel(const int* __restrict__ tokens, const float* __restrict__ emb) {
    int idx = blockIdx.x * 256 + threadIdx.x;     // B*256*128 units of 8 elems
    if (idx >= Bd * 256 * 128) return;
    int u = idx & 127, t = idx >> 7;
    int b = t >> 8, l = t & 255;
    int tok = tokens[t];
    const float* s = emb + (size_t)tok * Hd + u * 8;
    float f[8];
    *(float4*)f       = *(const float4*)s;
    *(float4*)(f + 4) = *(const float4*)(s + 4);
    int r = b * 128 + (l >> 1);
    size_t off = (size_t)r * KTOT + (l & 1) * 1024 + u * 8;
    *(uint4*)(g_Ah + off) = cvt8h(f);
}

// ---------------------------------------------------------------------------
// HMMA GEMM, warp-specialized: pre(M,5120) = A(M,2048) @ W^T, fp16, fp32 acc.
// CTA 128M x 128N. 8 consumer warps (4x2, 32x64 tiles) + 2 producer warps.
// 5-stage mbarrier ring (full: count 64 via cp.async.mbarrier.arrive.noinc;
// empty: count 8, one arrive per consumer warp). NO CTA-wide barrier in the
// mainloop -- warp skew and L2 latency absorbed by ring depth.
// ---------------------------------------------------------------------------
__global__ __launch_bounds__(320, 1)
void gemm_kernel(int level) {
    extern __shared__ char smraw[];
    const uint32_t smb = smem_u32(smraw);
    const uint32_t full0 = smb, empty0 = smb + 64;
    const uint32_t stg0 = smb + SMEM_BARS;
    const int tid = threadIdx.x, lane = tid & 31, wid = tid >> 5;
    const int M = Bd * (128 >> level);
    const int mt = blockIdx.x, bn = blockIdx.y;
    const size_t aRow0 = (size_t)(16384 - (16384 >> level)) + (size_t)mt * 128;
    const size_t bRow0 = (size_t)bn * 128;

    if (tid == 0) {
#pragma unroll
        for (int s = 0; s < NSTAGE; s++) {
            mbar_init(full0 + s * 8, 64);
            mbar_init(empty0 + s * 8, 8);
        }
        asm volatile("fence.proxy.async.shared::cta;" ::: "memory");
    }
    __syncthreads();

    if (wid >= 8) {
        // ---- producer: 2 warps, 64 threads ----
        const int ptid = tid - 256;          // 0..63
        const int lc = ptid & 7;             // 16B chunk in row
        const int lr = ptid >> 3;            // 0..7
        int stage = 0, phase = 1;            // phase=1: first empty-wait passes
        for (int it = 0; it < 32; it++) {
            mbar_wait(empty0 + stage * 8, phase);
            uint32_t st = stg0 + stage * STAGE_BYTES;
            int kb = it * 64;
#pragma unroll
            for (int i = 0; i < 16; i++) {           // A: 128 rows
                int row = lr + i * 8;
                cpasync16(st + row * PITCH + lc * 16,
                          g_Ah + (aRow0 + row) * KTOT + kb + lc * 8);
            }
#pragma unroll
            for (int i = 0; i < 16; i++) {           // B: 128 rows
                int row = lr + i * 8;
                cpasync16(st + STAGE_A + row * PITCH + lc * 16,
                          g_Wh + (bRow0 + row) * KTOT + kb + lc * 8);
            }
            cpasync_mbar_arrive(full0 + stage * 8);
            if (++stage == NSTAGE) { stage = 0; phase ^= 1; }
        }
        return;
    }

    // ---- consumers: 8 warps, 4x2, warp tile 32x64 ----
    const int wm = wid >> 1, wn = wid & 1;

    float acc[2][8][4];
#pragma unroll
    for (int a = 0; a < 2; a++)
#pragma unroll
        for (int b = 0; b < 8; b++)
#pragma unroll
            for (int c = 0; c < 4; c++) acc[a][b][c] = 0.0f;

    const uint32_t aB = stg0 + (wm * 32 + (lane & 15)) * PITCH + (lane >> 4) * 16;
    const uint32_t bB = stg0 + STAGE_A
                      + (wn * 64 + (lane & 7) + ((lane >> 4) << 3)) * PITCH
                      + ((lane >> 3) & 1) * 16;

    int stage = 0, phase = 0;
    for (int it = 0; it < 32; it++) {
        mbar_wait(full0 + stage * 8, phase);
        uint32_t sOff = (uint32_t)stage * STAGE_BYTES;
#pragma unroll
        for (int sub = 0; sub < 4; sub++) {
            uint32_t aS = aB + sOff + sub * 32;
            uint32_t bS = bB + sOff + sub * 32;
            uint32_t ah[2][4], bf[4][4];
            ldsm4(ah[0], aS);
            ldsm4(ah[1], aS + 16 * PITCH);
#pragma unroll
            for (int nbp = 0; nbp < 4; nbp++)
                ldsm4(bf[nbp], bS + nbp * 16 * PITCH);
#pragma unroll
            for (int nbp = 0; nbp < 4; nbp++)
#pragma unroll
                for (int mb = 0; mb < 2; mb++) {
                    mma16816(acc[mb][2*nbp],   ah[mb], bf[nbp]);
                    mma16816(acc[mb][2*nbp+1], ah[mb], bf[nbp] + 2);
                }
        }
        if (lane == 0) mbar_arrive(empty0 + stage * 8);
        if (++stage == NSTAGE) { stage = 0; phase ^= 1; }
    }

    // epilogue: direct STG (guarded for M=64 tail level)
    const int gm0 = mt * 128 + wm * 32;
    const int gn0 = bn * 128 + wn * 64;
#pragma unroll
    for (int mb = 0; mb < 2; mb++) {
        int r0 = gm0 + mb * 16 + (lane >> 2);
#pragma unroll
        for (int nb = 0; nb < 8; nb++) {
            int cc = gn0 + nb * 8 + (lane & 3) * 2;
            if (r0 < M) {
                float2 v = make_float2(acc[mb][nb][0], acc[mb][nb][1]);
                *(float2*)(g_pre + (size_t)r0 * NDIM + cc) = v;
            }
            if (r0 + 8 < M) {
                float2 v = make_float2(acc[mb][nb][2], acc[mb][nb][3]);
                *(float2*)(g_pre + (size_t)(r0 + 8) * NDIM + cc) = v;
            }
        }
    }
}

// ---------------------------------------------------------------------------
// Gates: bias + LSTM gate math; writes h (fp32) to d_out, c to ping-pong,
// and h as next-level A rows (fp16).
// ---------------------------------------------------------------------------
__global__ __launch_bounds__(256)
void gates_kernel(float* __restrict__ dout, int level) {
    const int P = 128 >> level;
    const int M = Bd * P;
    int idx = blockIdx.x * 256 + threadIdx.x;
    if (idx >= M * 128) return;
    int m = idx >> 7, u = idx & 127;
    int col0 = u << 3;

    const float* prow = g_pre + (size_t)m * NDIM + col0;
    float pi[8], po[8], pk[8], pl[8], pr[8];
    *(float4*)pi = *(const float4*)(prow);          *(float4*)(pi+4) = *(const float4*)(prow + 4);
    *(float4*)po = *(const float4*)(prow + 1024);   *(float4*)(po+4) = *(const float4*)(prow + 1028);
    *(float4*)pk = *(const float4*)(prow + 2048);   *(float4*)(pk+4) = *(const float4*)(prow + 2052);
    *(float4*)pl = *(const float4*)(prow + 3072);   *(float4*)(pl+4) = *(const float4*)(prow + 3076);
    *(float4*)pr = *(const float4*)(prow + 4096);   *(float4*)(pr+4) = *(const float4*)(prow + 4100);

    const float* bb = g_bcat + col0;
    float bi[8], bo[8], bk[8], bl[8], br[8];
    *(float4*)bi = *(const float4*)(bb);          *(float4*)(bi+4) = *(const float4*)(bb + 4);
    *(float4*)bo = *(const float4*)(bb + 1024);   *(float4*)(bo+4) = *(const float4*)(bb + 1028);
    *(float4*)bk = *(const float4*)(bb + 2048);   *(float4*)(bk+4) = *(const float4*)(bb + 2052);
    *(float4*)bl = *(const float4*)(bb + 3072);   *(float4*)(bl+4) = *(const float4*)(bb + 3076);
    *(float4*)br = *(const float4*)(bb + 4096);   *(float4*)(br+4) = *(const float4*)(bb + 4100);

    float cl[8] = {0,0,0,0,0,0,0,0}, cr[8] = {0,0,0,0,0,0,0,0};
    if (level > 0) {
        const float* cp = g_cbuf[(level + 1) & 1] + (size_t)m * 2048 + col0;
        *(float4*)cl = *(const float4*)(cp);         *(float4*)(cl+4) = *(const float4*)(cp + 4);
        *(float4*)cr = *(const float4*)(cp + 1024);  *(float4*)(cr+4) = *(const float4*)(cp + 1028);
    }

    float cv[8], hv[8];
#pragma unroll
    for (int i = 0; i < 8; i++) {
        float c = sigf(pi[i] + bi[i]) * tanhf_(pk[i] + bk[i])
                + sigf(pl[i] + bl[i]) * cl[i]
                + sigf(pr[i] + br[i]) * cr[i];
        cv[i] = c;
        hv[i] = sigf(po[i] + bo[i]) * tanhf_(c);
    }

    float* cw = g_cbuf[level & 1] + (size_t)m * Hd + col0;
    *(float4*)cw = *(const float4*)cv;  *(float4*)(cw + 4) = *(const float4*)(cv + 4);

    int b = m >> (7 - level);
    int j = m & (P - 1);
    int off = 256 - (256 >> level);
    float* hw = dout + ((size_t)b * FOREST + off + j) * Hd + col0;
    *(float4*)hw = *(const float4*)hv;  *(float4*)(hw + 4) = *(const float4*)(hv + 4);

    if (level < 7) {
        int r = b * (P >> 1) + (j >> 1);
        size_t rowbase = 16384 - (16384 >> (level + 1));
        size_t aoff = (rowbase + r) * (size_t)KTOT + (j & 1) * 1024 + col0;
        *(uint4*)(g_Ah + aoff) = cvt8h(hv);
    } else {
        float* hroot = dout + (size_t)Bd * FOREST * Hd + (size_t)m * Hd + col0;
        float* croot = hroot + (size_t)Bd * Hd;
        *(float4*)hroot = *(const float4*)hv;  *(float4*)(hroot + 4) = *(const float4*)(hv + 4);
        *(float4*)croot = *(const float4*)cv;  *(float4*)(croot + 4) = *(const float4*)(cv + 4);
    }
}

// ---------------------------------------------------------------------------
// launcher (graph-capturable: kernel launches only, default stream)
// ---------------------------------------------------------------------------
extern "C" void kernel_launch(void* const* d_in, const int* in_sizes, int n_in,
                              void* d_out, int out_size) {
    const int*   tokens = (const int*)  d_in[0];
    const float* emb    = (const float*)d_in[1];
    const float* W_iock = (const float*)d_in[2];
    const float* b_iock = (const float*)d_in[3];
    const float* U_iock = (const float*)d_in[4];
    const float* W_fl   = (const float*)d_in[5];
    const float* b_fl   = (const float*)d_in[6];
    const float* U_fl   = (const float*)d_in[7];
    const float* W_fr   = (const float*)d_in[8];
    const float* b_fr   = (const float*)d_in[9];
    const float* U_fr   = (const float*)d_in[10];
    float* out = (float*)d_out;

    static bool attr_set = false;
    if (!attr_set) {
        cudaFuncSetAttribute(gemm_kernel, cudaFuncAttributeMaxDynamicSharedMemorySize, SMEMT);
        attr_set = true;
    }

    pack_w_kernel<<<dim3(32, 80), 256>>>(W_iock, U_iock, W_fl, U_fl, W_fr, U_fr);
    pack_b_kernel<<<20, 256>>>(b_iock, b_fl, b_fr);
    {
        int total = Bd * 256 * 128;
        embed_kernel<<<(total + 255) / 256, 256>>>(tokens, emb);
    }
    for (int level = 0; level < 8; ++level) {
        int M = Bd * (128 >> level);
        dim3 grid((M + 127) / 128, 40);
        gemm_kernel<<<grid, 320, SMEMT>>>(level);
        int units = M * 128;
        gates_kernel<<<(units + 255) / 256, 256>>>(out, level);
    }
}